// round 2
// baseline (speedup 1.0000x reference)
#include <cuda_runtime.h>
#include <cuda_bf16.h>

// Problem constants (fixed by the dataset)
#define NN 25000     // nodes
#define NE 400000    // edges
#define NG 64        // graphs
#define F0 128       // input features
#define F1 512       // hidden features

// ---------------- scratch (device globals; no allocs allowed) ----------------
__device__ float g_agg1[NN * F0];        // 12.8 MB
__device__ float g_h1[NN * F1];          // 51.2 MB
__device__ float g_agg2[NN * F1];        // 51.2 MB
__device__ float g_h2[NN * F1];          // 51.2 MB
__device__ int   g_deg[NN];
__device__ int   g_cursor[NN];
__device__ int   g_rowptr[NN + 1];
__device__ int   g_srcs[NE];
__device__ float g_wgts[NE];
__device__ int   g_start[NG + 1];
__device__ float g_gv[NG * F1];

// ---------------- CSR build ----------------
__global__ void k_zero_counts() {
    int i = blockIdx.x * blockDim.x + threadIdx.x;
    if (i < NN) { g_deg[i] = 0; g_cursor[i] = 0; }
}

__global__ void k_hist(const int* __restrict__ ei) {
    int e = blockIdx.x * blockDim.x + threadIdx.x;
    if (e < NE) atomicAdd(&g_deg[ei[NE + e]], 1);
}

// single-block exclusive scan of g_deg -> g_rowptr (1024 threads, 25 elems each)
__global__ void k_scan() {
    __shared__ int s[1024];
    const int CH = (NN + 1023) / 1024;  // 25
    int t = threadIdx.x;
    int base = t * CH;
    int sum = 0;
    for (int i = 0; i < CH; i++) {
        int idx = base + i;
        sum += (idx < NN) ? g_deg[idx] : 0;
    }
    s[t] = sum;
    __syncthreads();
    // Hillis-Steele inclusive scan
    for (int off = 1; off < 1024; off <<= 1) {
        int v = (t >= off) ? s[t - off] : 0;
        __syncthreads();
        s[t] += v;
        __syncthreads();
    }
    int run = (t == 0) ? 0 : s[t - 1];
    for (int i = 0; i < CH; i++) {
        int idx = base + i;
        if (idx < NN) { g_rowptr[idx] = run; run += g_deg[idx]; }
    }
    if (t == 1023) g_rowptr[NN] = s[1023];
}

__global__ void k_scatter(const int* __restrict__ ei,
                          const float* __restrict__ ea) {
    int e = blockIdx.x * blockDim.x + threadIdx.x;
    if (e >= NE) return;
    int src = ei[e];
    int dst = ei[NE + e];
    int pos = g_rowptr[dst] + atomicAdd(&g_cursor[dst], 1);
    g_srcs[pos] = src;
    g_wgts[pos] = ea[e];
}

// ---------------- aggregation (gather-side, atomic-free) ----------------
// F=128: one warp per node, lane owns a float4 (4 feats)
__global__ void k_agg128(const float* __restrict__ x) {
    int node = blockIdx.x * 4 + (threadIdx.x >> 5);
    if (node >= NN) return;
    int lane = threadIdx.x & 31;
    int beg = g_rowptr[node], end = g_rowptr[node + 1];
    float4 acc = make_float4(0.f, 0.f, 0.f, 0.f);
    for (int p = beg; p < end; p++) {
        int s = g_srcs[p];
        float w = g_wgts[p];
        float4 v = *reinterpret_cast<const float4*>(&x[s * F0 + lane * 4]);
        acc.x += w * v.x; acc.y += w * v.y; acc.z += w * v.z; acc.w += w * v.w;
    }
    *reinterpret_cast<float4*>(&g_agg1[node * F0 + lane * 4]) = acc;
}

// F=512: one 128-thread block per node, thread owns a float4
__global__ void k_agg512() {
    int node = blockIdx.x;
    int f4 = threadIdx.x;  // 0..127
    int beg = g_rowptr[node], end = g_rowptr[node + 1];
    float4 acc = make_float4(0.f, 0.f, 0.f, 0.f);
    for (int p = beg; p < end; p++) {
        int s = g_srcs[p];
        float w = g_wgts[p];
        float4 v = *reinterpret_cast<const float4*>(&g_h1[s * F1 + f4 * 4]);
        acc.x += w * v.x; acc.y += w * v.y; acc.z += w * v.z; acc.w += w * v.w;
    }
    *reinterpret_cast<float4*>(&g_agg2[node * F1 + f4 * 4]) = acc;
}

// ---------------- fused dual GEMM: C = relu(A1@B1 + A2@B2 + bias) ----------------
// 64x64 block tile, BK=16, 256 threads, 4x4 microtile per thread
__global__ void k_gemm_dual(const float* __restrict__ A1, const float* __restrict__ B1, int K1,
                            const float* __restrict__ A2, const float* __restrict__ B2, int K2,
                            const float* __restrict__ bias, float* __restrict__ C,
                            int M, int Nc) {
    __shared__ float As[16][64];
    __shared__ float Bs[16][64];
    int tid = threadIdx.x;
    int tx = tid & 15, ty = tid >> 4;
    int m0 = blockIdx.y * 64;
    int n0 = blockIdx.x * 64;

    float acc[4][4];
#pragma unroll
    for (int i = 0; i < 4; i++)
#pragma unroll
        for (int j = 0; j < 4; j++) acc[i][j] = 0.f;

    int arow = tid >> 2;       // 0..63
    int akq  = tid & 3;        // 0..3 (float4 within the 16-wide K slice)
    int bkr  = tid >> 4;       // 0..15
    int bnq  = tid & 15;       // 0..15 (float4 within 64-wide N slice)

    for (int phase = 0; phase < 2; phase++) {
        const float* A = phase ? A2 : A1;
        const float* B = phase ? B2 : B1;
        int K = phase ? K2 : K1;
        for (int kk = 0; kk < K; kk += 16) {
            // load A tile (64 x 16), store k-major
            float4 av = make_float4(0.f, 0.f, 0.f, 0.f);
            if (m0 + arow < M)
                av = *reinterpret_cast<const float4*>(&A[(size_t)(m0 + arow) * K + kk + akq * 4]);
            As[akq * 4 + 0][arow] = av.x;
            As[akq * 4 + 1][arow] = av.y;
            As[akq * 4 + 2][arow] = av.z;
            As[akq * 4 + 3][arow] = av.w;
            // load B tile (16 x 64)
            float4 bv = *reinterpret_cast<const float4*>(&B[(size_t)(kk + bkr) * Nc + n0 + bnq * 4]);
            *reinterpret_cast<float4*>(&Bs[bkr][bnq * 4]) = bv;
            __syncthreads();
#pragma unroll
            for (int k = 0; k < 16; k++) {
                float4 a = *reinterpret_cast<const float4*>(&As[k][ty * 4]);
                float4 b = *reinterpret_cast<const float4*>(&Bs[k][tx * 4]);
                float ar[4] = {a.x, a.y, a.z, a.w};
                float br[4] = {b.x, b.y, b.z, b.w};
#pragma unroll
                for (int i = 0; i < 4; i++)
#pragma unroll
                    for (int j = 0; j < 4; j++) acc[i][j] += ar[i] * br[j];
            }
            __syncthreads();
        }
    }

    float4 bb = *reinterpret_cast<const float4*>(&bias[n0 + tx * 4]);
    float bias4[4] = {bb.x, bb.y, bb.z, bb.w};
#pragma unroll
    for (int i = 0; i < 4; i++) {
        int m = m0 + ty * 4 + i;
        if (m < M) {
            float4 out;
            out.x = fmaxf(acc[i][0] + bias4[0], 0.f);
            out.y = fmaxf(acc[i][1] + bias4[1], 0.f);
            out.z = fmaxf(acc[i][2] + bias4[2], 0.f);
            out.w = fmaxf(acc[i][3] + bias4[3], 0.f);
            *reinterpret_cast<float4*>(&C[(size_t)m * Nc + n0 + tx * 4]) = out;
        }
    }
}

// ---------------- pooling (batch_ids sorted -> segment boundaries) ----------------
__global__ void k_bounds(const int* __restrict__ batch) {
    int g = threadIdx.x;
    if (g > NG) return;
    int lo = 0, hi = NN;
    while (lo < hi) {
        int mid = (lo + hi) >> 1;
        if (batch[mid] < g) lo = mid + 1; else hi = mid;
    }
    g_start[g] = lo;
}

__global__ void k_pool() {
    int g = blockIdx.x >> 2;
    int f = ((blockIdx.x & 3) << 7) + threadIdx.x;
    int s0 = g_start[g], s1 = g_start[g + 1];
    float acc = 0.f;
    for (int n = s0; n < s1; n++) acc += g_h2[(size_t)n * F1 + f];
    float c = fmaxf((float)(s1 - s0), 1.0f);
    g_gv[g * F1 + f] = acc / c;
}

// ---------------- tiny MLP head: 512 -> 64 -> 16 -> 1 ----------------
__global__ void k_mlp(const float* __restrict__ Wl1, const float* __restrict__ bl1,
                      const float* __restrict__ Wl2, const float* __restrict__ bl2,
                      const float* __restrict__ Wl3, const float* __restrict__ bl3,
                      float* __restrict__ out) {
    int g = blockIdx.x;
    int t = threadIdx.x;  // 64 threads
    __shared__ float gv[F1];
    __shared__ float t1[64];
    __shared__ float t2[16];
    for (int i = t; i < F1; i += 64) gv[i] = g_gv[g * F1 + i];
    __syncthreads();
    float a = bl1[t];
    for (int k = 0; k < F1; k++) a += gv[k] * Wl1[k * 64 + t];
    t1[t] = fmaxf(a, 0.f);
    __syncthreads();
    if (t < 16) {
        float a2 = bl2[t];
        for (int k = 0; k < 64; k++) a2 += t1[k] * Wl2[k * 16 + t];
        t2[t] = fmaxf(a2, 0.f);
    }
    __syncthreads();
    if (t == 0) {
        float a3 = bl3[0];
        for (int k = 0; k < 16; k++) a3 += t2[k] * Wl3[k];
        out[g] = a3;
    }
}

// ---------------- launch ----------------
extern "C" void kernel_launch(void* const* d_in, const int* in_sizes, int n_in,
                              void* d_out, int out_size) {
    const float* x       = (const float*)d_in[0];
    const int*   ei      = (const int*)d_in[1];    // int32 (JAX x64 disabled)
    const float* ea      = (const float*)d_in[2];
    const int*   batch   = (const int*)d_in[3];    // int32
    const float* W1_rel  = (const float*)d_in[4];
    const float* b1      = (const float*)d_in[5];
    const float* W1_root = (const float*)d_in[6];
    const float* W2_rel  = (const float*)d_in[7];
    const float* b2      = (const float*)d_in[8];
    const float* W2_root = (const float*)d_in[9];
    const float* Wl1     = (const float*)d_in[10];
    const float* bl1     = (const float*)d_in[11];
    const float* Wl2     = (const float*)d_in[12];
    const float* bl2     = (const float*)d_in[13];
    const float* Wl3     = (const float*)d_in[14];
    const float* bl3     = (const float*)d_in[15];
    float* out = (float*)d_out;

    float* agg1; cudaGetSymbolAddress((void**)&agg1, g_agg1);
    float* h1;   cudaGetSymbolAddress((void**)&h1,   g_h1);
    float* agg2; cudaGetSymbolAddress((void**)&agg2, g_agg2);
    float* h2;   cudaGetSymbolAddress((void**)&h2,   g_h2);

    // CSR build
    k_zero_counts<<<(NN + 255) / 256, 256>>>();
    k_hist<<<(NE + 255) / 256, 256>>>(ei);
    k_scan<<<1, 1024>>>();
    k_scatter<<<(NE + 255) / 256, 256>>>(ei, ea);

    // layer 1
    k_agg128<<<(NN + 3) / 4, 128>>>(x);
    {
        dim3 grid(F1 / 64, (NN + 63) / 64);
        k_gemm_dual<<<grid, 256>>>(agg1, W1_rel, F0, x, W1_root, F0, b1, h1, NN, F1);
    }
    // layer 2
    k_agg512<<<NN, 128>>>();
    {
        dim3 grid(F1 / 64, (NN + 63) / 64);
        k_gemm_dual<<<grid, 256>>>(agg2, W2_rel, F1, h1, W2_root, F1, b2, h2, NN, F1);
    }
    // pool + head
    k_bounds<<<1, NG + 1>>>(batch);
    k_pool<<<NG * 4, 128>>>();
    k_mlp<<<NG, 64>>>(Wl1, bl1, Wl2, bl2, Wl3, bl3, out);
    (void)in_sizes; (void)n_in; (void)out_size;
}

// round 4
// speedup vs baseline: 1.5909x; 1.5909x over previous
#include <cuda_runtime.h>
#include <cuda_bf16.h>
#include <cstdint>

#define NN 25000
#define NE 400000
#define NG 64
#define F0 128
#define F1 512

// ================= device scratch (no allocs allowed) =================
__device__ __nv_bfloat16 g_xh[NN * F0], g_xl[NN * F0];
__device__ __nv_bfloat16 g_a1h[NN * F0], g_a1l[NN * F0];
__device__ float         g_h1f[NN * F1];
__device__ __nv_bfloat16 g_h1h[NN * F1], g_h1l[NN * F1];
__device__ __nv_bfloat16 g_a2h[NN * F1], g_a2l[NN * F1];
__device__ float         g_h2f[NN * F1];
__device__ __nv_bfloat16 g_w1rh[F1 * F0], g_w1rl[F1 * F0];  // W1_rel^T  [512][128]
__device__ __nv_bfloat16 g_w1th[F1 * F0], g_w1tl[F1 * F0];  // W1_root^T [512][128]
__device__ __nv_bfloat16 g_w2rh[F1 * F1], g_w2rl[F1 * F1];  // W2_rel^T  [512][512]
__device__ __nv_bfloat16 g_w2th[F1 * F1], g_w2tl[F1 * F1];  // W2_root^T [512][512]
__device__ int   g_deg[NN], g_cursor[NN], g_rowptr[NN + 1], g_srcs[NE];
__device__ float g_wgts[NE];
__device__ int   g_start[NG + 1];
__device__ float g_gv[NG * F1];

// ================= helpers =================
__device__ __forceinline__ uint32_t smem_u32(const void* p) {
    uint32_t a;
    asm("{ .reg .u64 t; cvta.to.shared.u64 t, %1; cvt.u32.u64 %0, t; }" : "=r"(a) : "l"(p));
    return a;
}
__device__ __forceinline__ void ldm_x4(uint32_t* r, uint32_t addr) {
    asm volatile("ldmatrix.sync.aligned.m8n8.x4.shared.b16 {%0,%1,%2,%3}, [%4];"
                 : "=r"(r[0]), "=r"(r[1]), "=r"(r[2]), "=r"(r[3]) : "r"(addr));
}
__device__ __forceinline__ void ldm_x2(uint32_t* r, uint32_t addr) {
    asm volatile("ldmatrix.sync.aligned.m8n8.x2.shared.b16 {%0,%1}, [%2];"
                 : "=r"(r[0]), "=r"(r[1]) : "r"(addr));
}
__device__ __forceinline__ void mma_bf16(float* c, const uint32_t* a, const uint32_t* b) {
    asm volatile("mma.sync.aligned.m16n8k16.row.col.f32.bf16.bf16.f32 "
                 "{%0,%1,%2,%3}, {%4,%5,%6,%7}, {%8,%9}, {%0,%1,%2,%3};"
                 : "+f"(c[0]), "+f"(c[1]), "+f"(c[2]), "+f"(c[3])
                 : "r"(a[0]), "r"(a[1]), "r"(a[2]), "r"(a[3]), "r"(b[0]), "r"(b[1]));
}
__device__ __forceinline__ void split2(float v, __nv_bfloat16& h, __nv_bfloat16& l) {
    h = __float2bfloat16_rn(v);
    l = __float2bfloat16_rn(v - __bfloat162float(h));
}

// ================= CSR build =================
__global__ void k_zero_counts() {
    int i = blockIdx.x * blockDim.x + threadIdx.x;
    if (i < NN) { g_deg[i] = 0; g_cursor[i] = 0; }
}
__global__ void k_hist(const int* __restrict__ ei) {
    int e = blockIdx.x * blockDim.x + threadIdx.x;
    if (e < NE) atomicAdd(&g_deg[ei[NE + e]], 1);
}
__global__ void k_scan() {
    __shared__ int s[1024];
    const int CH = (NN + 1023) / 1024;
    int t = threadIdx.x, base = t * CH, sum = 0;
    for (int i = 0; i < CH; i++) { int idx = base + i; sum += (idx < NN) ? g_deg[idx] : 0; }
    s[t] = sum; __syncthreads();
    for (int off = 1; off < 1024; off <<= 1) {
        int v = (t >= off) ? s[t - off] : 0; __syncthreads();
        s[t] += v; __syncthreads();
    }
    int run = (t == 0) ? 0 : s[t - 1];
    for (int i = 0; i < CH; i++) {
        int idx = base + i;
        if (idx < NN) { g_rowptr[idx] = run; run += g_deg[idx]; }
    }
    if (t == 1023) g_rowptr[NN] = s[1023];
}
__global__ void k_scatter(const int* __restrict__ ei, const float* __restrict__ ea) {
    int e = blockIdx.x * blockDim.x + threadIdx.x;
    if (e >= NE) return;
    int src = ei[e], dst = ei[NE + e];
    int pos = g_rowptr[dst] + atomicAdd(&g_cursor[dst], 1);
    g_srcs[pos] = src; g_wgts[pos] = ea[e];
}

// ================= conversions =================
__global__ void k_split_x(const float* __restrict__ x) {
    int i = blockIdx.x * blockDim.x + threadIdx.x;
    if (i < NN * F0) split2(x[i], g_xh[i], g_xl[i]);
}
__global__ void k_split_wT(const float* __restrict__ W, __nv_bfloat16* __restrict__ th,
                           __nv_bfloat16* __restrict__ tl, int K, int N) {
    int i = blockIdx.x * blockDim.x + threadIdx.x;
    if (i >= K * N) return;
    int k = i / N, n = i % N;
    split2(W[i], th[n * K + k], tl[n * K + k]);
}

// ================= aggregation (gather-side, atomic-free) =================
__global__ void k_agg128(const float* __restrict__ x) {
    int node = blockIdx.x * 4 + (threadIdx.x >> 5);
    if (node >= NN) return;
    int lane = threadIdx.x & 31;
    int beg = g_rowptr[node], end = g_rowptr[node + 1];
    float4 acc = make_float4(0.f, 0.f, 0.f, 0.f);
    for (int p = beg; p < end; p++) {
        int s = g_srcs[p]; float w = g_wgts[p];
        float4 v = *reinterpret_cast<const float4*>(&x[s * F0 + lane * 4]);
        acc.x += w * v.x; acc.y += w * v.y; acc.z += w * v.z; acc.w += w * v.w;
    }
    int o = node * F0 + lane * 4;
    float a[4] = {acc.x, acc.y, acc.z, acc.w};
#pragma unroll
    for (int i = 0; i < 4; i++) split2(a[i], g_a1h[o + i], g_a1l[o + i]);
}
__global__ void k_agg512() {
    int node = blockIdx.x, f4 = threadIdx.x;
    int beg = g_rowptr[node], end = g_rowptr[node + 1];
    float4 acc = make_float4(0.f, 0.f, 0.f, 0.f);
    for (int p = beg; p < end; p++) {
        int s = g_srcs[p]; float w = g_wgts[p];
        float4 v = *reinterpret_cast<const float4*>(&g_h1f[(size_t)s * F1 + f4 * 4]);
        acc.x += w * v.x; acc.y += w * v.y; acc.z += w * v.z; acc.w += w * v.w;
    }
    size_t o = (size_t)node * F1 + f4 * 4;
    float a[4] = {acc.x, acc.y, acc.z, acc.w};
#pragma unroll
    for (int i = 0; i < 4; i++) split2(a[i], g_a2h[o + i], g_a2l[o + i]);
}

// ================= tensor-core dual GEMM (mma.sync bf16, split hi/lo) =================
// C = relu(A1@B1^T + A2@B2^T + bias). A: [M,K] hi/lo, B^T: [N,K] hi/lo.
// 3 MMA passes: Ah*Bh + Ah*Bl + Al*Bh. 128x128 tile, 8 warps (2x4), K-chunk 64.
#define CHK 64
#define PAD 72                      // bf16 row pitch in SMEM (conflict-free ldmatrix)
#define TILE_BYTES (128 * PAD * 2)  // 18432
#define SM_AH 0
#define SM_AL TILE_BYTES
#define SM_BH (2 * TILE_BYTES)
#define SM_BL (3 * TILE_BYTES)
#define SMEM_BYTES (4 * TILE_BYTES)  // 73728

__global__ __launch_bounds__(256) void k_gemm_tc(
    const __nv_bfloat16* __restrict__ A1h, const __nv_bfloat16* __restrict__ A1l,
    const __nv_bfloat16* __restrict__ B1h, const __nv_bfloat16* __restrict__ B1l,
    const __nv_bfloat16* __restrict__ A2h, const __nv_bfloat16* __restrict__ A2l,
    const __nv_bfloat16* __restrict__ B2h, const __nv_bfloat16* __restrict__ B2l,
    int K, const float* __restrict__ bias,
    float* __restrict__ Cf, __nv_bfloat16* __restrict__ Ch, __nv_bfloat16* __restrict__ Cl,
    int M, int Nc) {
    extern __shared__ char smem[];
    uint32_t sb = smem_u32(smem);
    int tid = threadIdx.x;
    int wid = tid >> 5, lane = tid & 31;
    int warpM = wid >> 2, warpN = wid & 3;   // 2 x 4
    int m0 = blockIdx.y * 128, n0 = blockIdx.x * 128;

    float acc[4][4][4];
#pragma unroll
    for (int i = 0; i < 4; i++)
#pragma unroll
        for (int j = 0; j < 4; j++)
#pragma unroll
            for (int q = 0; q < 4; q++) acc[i][j][q] = 0.f;

    int ncpp = K / CHK;          // chunks per phase
    int NC = 2 * ncpp;

    // ldmatrix source addresses (per-thread)
    uint32_t a_base = sb + ((lane & 15) * PAD + (lane >> 4) * 8) * 2;   // +tile row/col later
    uint32_t b_base = sb + ((lane & 7) * PAD + ((lane >> 3) & 1) * 8) * 2;

    for (int c = 0; c < NC; c++) {
        int ph = c / ncpp;
        int kk = (c % ncpp) * CHK;
        const __nv_bfloat16* Ah = ph ? A2h : A1h;
        const __nv_bfloat16* Al = ph ? A2l : A1l;
        const __nv_bfloat16* Bh = ph ? B2h : B1h;
        const __nv_bfloat16* Bl = ph ? B2l : B1l;

        if (c > 0) __syncthreads();   // previous chunk's ldmatrix done
        // load chunk: 4 arrays x 128 rows x 64 cols bf16
#pragma unroll
        for (int i = 0; i < 4; i++) {
            int unit = tid + i * 256;        // 0..1023
            int row = unit >> 3, q = unit & 7;
            uint32_t so = (uint32_t)(row * PAD + q * 8) * 2;
            int m = m0 + row;
            uint4 vah = make_uint4(0, 0, 0, 0), val = make_uint4(0, 0, 0, 0);
            if (m < M) {
                size_t ai = (size_t)m * K + kk + q * 8;
                vah = *reinterpret_cast<const uint4*>(Ah + ai);
                val = *reinterpret_cast<const uint4*>(Al + ai);
            }
            size_t bi = (size_t)(n0 + row) * K + kk + q * 8;
            *reinterpret_cast<uint4*>(smem + SM_AH + so) = vah;
            *reinterpret_cast<uint4*>(smem + SM_AL + so) = val;
            *reinterpret_cast<uint4*>(smem + SM_BH + so) = *reinterpret_cast<const uint4*>(Bh + bi);
            *reinterpret_cast<uint4*>(smem + SM_BL + so) = *reinterpret_cast<const uint4*>(Bl + bi);
        }
        __syncthreads();

#pragma unroll
        for (int ks = 0; ks < CHK / 16; ks++) {
            uint32_t bh[4][2], bl[4][2];
#pragma unroll
            for (int nt = 0; nt < 4; nt++) {
                uint32_t off = (uint32_t)((warpN * 32 + nt * 8) * PAD + ks * 16) * 2;
                ldm_x2(bh[nt], b_base + SM_BH + off);
                ldm_x2(bl[nt], b_base + SM_BL + off);
            }
#pragma unroll
            for (int mt = 0; mt < 4; mt++) {
                uint32_t ah[4], al[4];
                uint32_t off = (uint32_t)((warpM * 64 + mt * 16) * PAD + ks * 16) * 2;
                ldm_x4(ah, a_base + SM_AH + off);
                ldm_x4(al, a_base + SM_AL + off);
#pragma unroll
                for (int nt = 0; nt < 4; nt++) {
                    mma_bf16(acc[mt][nt], ah, bh[nt]);
                    mma_bf16(acc[mt][nt], ah, bl[nt]);
                    mma_bf16(acc[mt][nt], al, bh[nt]);
                }
            }
        }
    }

    // epilogue: bias + relu (+ optional hi/lo split for next layer)
#pragma unroll
    for (int mt = 0; mt < 4; mt++) {
#pragma unroll
        for (int nt = 0; nt < 4; nt++) {
            int n = n0 + warpN * 32 + nt * 8 + (lane & 3) * 2;
            float b0 = __ldg(&bias[n]), b1v = __ldg(&bias[n + 1]);
#pragma unroll
            for (int h = 0; h < 2; h++) {
                int m = m0 + warpM * 64 + mt * 16 + (lane >> 2) + h * 8;
                if (m < M) {
                    size_t o = (size_t)m * Nc + n;
                    float v0 = fmaxf(acc[mt][nt][h * 2 + 0] + b0, 0.f);
                    float v1 = fmaxf(acc[mt][nt][h * 2 + 1] + b1v, 0.f);
                    Cf[o] = v0; Cf[o + 1] = v1;
                    if (Ch) {
                        split2(v0, Ch[o], Cl[o]);
                        split2(v1, Ch[o + 1], Cl[o + 1]);
                    }
                }
            }
        }
    }
}

// ================= pooling + MLP head =================
__global__ void k_bounds(const int* __restrict__ batch) {
    int g = threadIdx.x;
    if (g > NG) return;
    int lo = 0, hi = NN;
    while (lo < hi) { int mid = (lo + hi) >> 1; if (batch[mid] < g) lo = mid + 1; else hi = mid; }
    g_start[g] = lo;
}
__global__ void k_pool() {
    int g = blockIdx.x >> 2;
    int f = ((blockIdx.x & 3) << 7) + threadIdx.x;
    int s0 = g_start[g], s1 = g_start[g + 1];
    float acc = 0.f;
    for (int n = s0; n < s1; n++) acc += g_h2f[(size_t)n * F1 + f];
    g_gv[g * F1 + f] = acc / fmaxf((float)(s1 - s0), 1.0f);
}
__global__ void k_mlp(const float* __restrict__ Wl1, const float* __restrict__ bl1,
                      const float* __restrict__ Wl2, const float* __restrict__ bl2,
                      const float* __restrict__ Wl3, const float* __restrict__ bl3,
                      float* __restrict__ out) {
    int g = blockIdx.x, t = threadIdx.x;
    __shared__ float gv[F1], t1[64], t2[16];
    for (int i = t; i < F1; i += 64) gv[i] = g_gv[g * F1 + i];
    __syncthreads();
    float a = bl1[t];
    for (int k = 0; k < F1; k++) a += gv[k] * Wl1[k * 64 + t];
    t1[t] = fmaxf(a, 0.f);
    __syncthreads();
    if (t < 16) {
        float a2 = bl2[t];
        for (int k = 0; k < 64; k++) a2 += t1[k] * Wl2[k * 16 + t];
        t2[t] = fmaxf(a2, 0.f);
    }
    __syncthreads();
    if (t == 0) {
        float a3 = bl3[0];
        for (int k = 0; k < 16; k++) a3 += t2[k] * Wl3[k];
        out[g] = a3;
    }
}

// ================= launch =================
extern "C" void kernel_launch(void* const* d_in, const int* in_sizes, int n_in,
                              void* d_out, int out_size) {
    const float* x       = (const float*)d_in[0];
    const int*   ei      = (const int*)d_in[1];
    const float* ea      = (const float*)d_in[2];
    const int*   batch   = (const int*)d_in[3];
    const float* W1_rel  = (const float*)d_in[4];
    const float* b1      = (const float*)d_in[5];
    const float* W1_root = (const float*)d_in[6];
    const float* W2_rel  = (const float*)d_in[7];
    const float* b2      = (const float*)d_in[8];
    const float* W2_root = (const float*)d_in[9];
    const float* Wl1     = (const float*)d_in[10];
    const float* bl1     = (const float*)d_in[11];
    const float* Wl2     = (const float*)d_in[12];
    const float* bl2     = (const float*)d_in[13];
    const float* Wl3     = (const float*)d_in[14];
    const float* bl3     = (const float*)d_in[15];
    float* out = (float*)d_out;

    cudaFuncSetAttribute(k_gemm_tc, cudaFuncAttributeMaxDynamicSharedMemorySize, SMEM_BYTES);

#define SYM(T, p, s) T* p; cudaGetSymbolAddress((void**)&p, s)
    SYM(__nv_bfloat16, xh, g_xh);   SYM(__nv_bfloat16, xl, g_xl);
    SYM(__nv_bfloat16, a1h, g_a1h); SYM(__nv_bfloat16, a1l, g_a1l);
    SYM(float, h1f, g_h1f);
    SYM(__nv_bfloat16, h1h, g_h1h); SYM(__nv_bfloat16, h1l, g_h1l);
    SYM(__nv_bfloat16, a2h, g_a2h); SYM(__nv_bfloat16, a2l, g_a2l);
    SYM(float, h2f, g_h2f);
    SYM(__nv_bfloat16, w1rh, g_w1rh); SYM(__nv_bfloat16, w1rl, g_w1rl);
    SYM(__nv_bfloat16, w1th, g_w1th); SYM(__nv_bfloat16, w1tl, g_w1tl);
    SYM(__nv_bfloat16, w2rh, g_w2rh); SYM(__nv_bfloat16, w2rl, g_w2rl);
    SYM(__nv_bfloat16, w2th, g_w2th); SYM(__nv_bfloat16, w2tl, g_w2tl);
#undef SYM

    // CSR build
    k_zero_counts<<<(NN + 255) / 256, 256>>>();
    k_hist<<<(NE + 255) / 256, 256>>>(ei);
    k_scan<<<1, 1024>>>();
    k_scatter<<<(NE + 255) / 256, 256>>>(ei, ea);

    // precision splits (x + transposed weights)
    k_split_x<<<(NN * F0 + 255) / 256, 256>>>(x);
    k_split_wT<<<(F0 * F1 + 255) / 256, 256>>>(W1_rel, w1rh, w1rl, F0, F1);
    k_split_wT<<<(F0 * F1 + 255) / 256, 256>>>(W1_root, w1th, w1tl, F0, F1);
    k_split_wT<<<(F1 * F1 + 255) / 256, 256>>>(W2_rel, w2rh, w2rl, F1, F1);
    k_split_wT<<<(F1 * F1 + 255) / 256, 256>>>(W2_root, w2th, w2tl, F1, F1);

    // layer 1: h1 = relu(agg1@W1_rel + x@W1_root + b1)
    k_agg128<<<(NN + 3) / 4, 128>>>(x);
    {
        dim3 grid(F1 / 128, (NN + 127) / 128);
        k_gemm_tc<<<grid, 256, SMEM_BYTES>>>(a1h, a1l, w1rh, w1rl, xh, xl, w1th, w1tl,
                                             F0, b1, h1f, h1h, h1l, NN, F1);
    }
    // layer 2: h2 = relu(agg2@W2_rel + h1@W2_root + b2)
    k_agg512<<<NN, 128>>>();
    {
        dim3 grid(F1 / 128, (NN + 127) / 128);
        k_gemm_tc<<<grid, 256, SMEM_BYTES>>>(a2h, a2l, w2rh, w2rl, h1h, h1l, w2th, w2tl,
                                             F1, b2, h2f, ((__nv_bfloat16*)0), ((__nv_bfloat16*)0),
                                             NN, F1);
    }
    // pool + head
    k_bounds<<<1, NG + 1>>>(batch);
    k_pool<<<NG * 4, 128>>>();
    k_mlp<<<NG, 64>>>(Wl1, bl1, Wl2, bl2, Wl3, bl3, out);
    (void)in_sizes; (void)n_in; (void)out_size;
}

// round 5
// speedup vs baseline: 1.7569x; 1.1043x over previous
#include <cuda_runtime.h>
#include <cuda_bf16.h>
#include <cstdint>

#define NN 25000
#define NE 400000
#define NG 64
#define F0 128
#define F1 512

// ================= device scratch (no allocs allowed) =================
__device__ __nv_bfloat16 g_xh[NN * F0], g_xl[NN * F0];
__device__ __nv_bfloat16 g_a1h[NN * F0], g_a1l[NN * F0];
__device__ float         g_h1f[NN * F1];
__device__ __nv_bfloat16 g_h1h[NN * F1], g_h1l[NN * F1];
__device__ __nv_bfloat16 g_a2h[NN * F1], g_a2l[NN * F1];
__device__ float         g_h2f[NN * F1];
__device__ __nv_bfloat16 g_w1rh[F1 * F0], g_w1rl[F1 * F0];
__device__ __nv_bfloat16 g_w1th[F1 * F0], g_w1tl[F1 * F0];
__device__ __nv_bfloat16 g_w2rh[F1 * F1], g_w2rl[F1 * F1];
__device__ __nv_bfloat16 g_w2th[F1 * F1], g_w2tl[F1 * F1];
__device__ int   g_deg[NN], g_cursor[NN], g_rowptr[NN + 1], g_srcs[NE];
__device__ float g_wgts[NE];
__device__ int   g_start[NG + 1];
__device__ float g_gv[NG * F1];

// ================= helpers =================
__device__ __forceinline__ uint32_t smem_u32(const void* p) {
    uint32_t a;
    asm("{ .reg .u64 t; cvta.to.shared.u64 t, %1; cvt.u32.u64 %0, t; }" : "=r"(a) : "l"(p));
    return a;
}
__device__ __forceinline__ void ldm_x4(uint32_t* r, uint32_t addr) {
    asm volatile("ldmatrix.sync.aligned.m8n8.x4.shared.b16 {%0,%1,%2,%3}, [%4];"
                 : "=r"(r[0]), "=r"(r[1]), "=r"(r[2]), "=r"(r[3]) : "r"(addr));
}
__device__ __forceinline__ void ldm_x2(uint32_t* r, uint32_t addr) {
    asm volatile("ldmatrix.sync.aligned.m8n8.x2.shared.b16 {%0,%1}, [%2];"
                 : "=r"(r[0]), "=r"(r[1]) : "r"(addr));
}
__device__ __forceinline__ void mma_bf16(float* c, const uint32_t* a, const uint32_t* b) {
    asm volatile("mma.sync.aligned.m16n8k16.row.col.f32.bf16.bf16.f32 "
                 "{%0,%1,%2,%3}, {%4,%5,%6,%7}, {%8,%9}, {%0,%1,%2,%3};"
                 : "+f"(c[0]), "+f"(c[1]), "+f"(c[2]), "+f"(c[3])
                 : "r"(a[0]), "r"(a[1]), "r"(a[2]), "r"(a[3]), "r"(b[0]), "r"(b[1]));
}
__device__ __forceinline__ void cpa16(uint32_t dst, const __nv_bfloat16* src, uint32_t sz) {
    asm volatile("cp.async.cg.shared.global [%0], [%1], 16, %2;"
                 :: "r"(dst), "l"(__cvta_generic_to_global(src)), "r"(sz) : "memory");
}
__device__ __forceinline__ void cp_commit() {
    asm volatile("cp.async.commit_group;" ::: "memory");
}
template <int N>
__device__ __forceinline__ void cp_wait() {
    asm volatile("cp.async.wait_group %0;" :: "n"(N) : "memory");
}
__device__ __forceinline__ void split2(float v, __nv_bfloat16& h, __nv_bfloat16& l) {
    h = __float2bfloat16_rn(v);
    l = __float2bfloat16_rn(v - __bfloat162float(h));
}

// ================= CSR build =================
__global__ void k_zero_counts() {
    int i = blockIdx.x * blockDim.x + threadIdx.x;
    if (i < NN) { g_deg[i] = 0; g_cursor[i] = 0; }
}
__global__ void k_hist(const int* __restrict__ ei) {
    int e = blockIdx.x * blockDim.x + threadIdx.x;
    if (e < NE) atomicAdd(&g_deg[ei[NE + e]], 1);
}
__global__ void k_scan() {
    __shared__ int s[1024];
    const int CH = (NN + 1023) / 1024;
    int t = threadIdx.x, base = t * CH, sum = 0;
    for (int i = 0; i < CH; i++) { int idx = base + i; sum += (idx < NN) ? g_deg[idx] : 0; }
    s[t] = sum; __syncthreads();
    for (int off = 1; off < 1024; off <<= 1) {
        int v = (t >= off) ? s[t - off] : 0; __syncthreads();
        s[t] += v; __syncthreads();
    }
    int run = (t == 0) ? 0 : s[t - 1];
    for (int i = 0; i < CH; i++) {
        int idx = base + i;
        if (idx < NN) { g_rowptr[idx] = run; run += g_deg[idx]; }
    }
    if (t == 1023) g_rowptr[NN] = s[1023];
}
__global__ void k_scatter(const int* __restrict__ ei, const float* __restrict__ ea) {
    int e = blockIdx.x * blockDim.x + threadIdx.x;
    if (e >= NE) return;
    int src = ei[e], dst = ei[NE + e];
    int pos = g_rowptr[dst] + atomicAdd(&g_cursor[dst], 1);
    g_srcs[pos] = src; g_wgts[pos] = ea[e];
}

// ================= conversions =================
__global__ void k_split_x(const float* __restrict__ x) {
    int i = blockIdx.x * blockDim.x + threadIdx.x;
    if (i < NN * F0) split2(x[i], g_xh[i], g_xl[i]);
}
__global__ void k_split_wT(const float* __restrict__ W, __nv_bfloat16* __restrict__ th,
                           __nv_bfloat16* __restrict__ tl, int K, int N) {
    int i = blockIdx.x * blockDim.x + threadIdx.x;
    if (i >= K * N) return;
    int k = i / N, n = i % N;
    split2(W[i], th[n * K + k], tl[n * K + k]);
}

// ================= aggregation (gather-side, atomic-free) =================
__global__ void k_agg128(const float* __restrict__ x) {
    int node = blockIdx.x * 4 + (threadIdx.x >> 5);
    if (node >= NN) return;
    int lane = threadIdx.x & 31;
    int beg = g_rowptr[node], end = g_rowptr[node + 1];
    float4 acc = make_float4(0.f, 0.f, 0.f, 0.f);
    for (int p = beg; p < end; p++) {
        int s = g_srcs[p]; float w = g_wgts[p];
        float4 v = *reinterpret_cast<const float4*>(&x[s * F0 + lane * 4]);
        acc.x += w * v.x; acc.y += w * v.y; acc.z += w * v.z; acc.w += w * v.w;
    }
    int o = node * F0 + lane * 4;
    float a[4] = {acc.x, acc.y, acc.z, acc.w};
#pragma unroll
    for (int i = 0; i < 4; i++) split2(a[i], g_a1h[o + i], g_a1l[o + i]);
}
__global__ void k_agg512() {
    int node = blockIdx.x, f4 = threadIdx.x;
    int beg = g_rowptr[node], end = g_rowptr[node + 1];
    float4 acc = make_float4(0.f, 0.f, 0.f, 0.f);
    for (int p = beg; p < end; p++) {
        int s = g_srcs[p]; float w = g_wgts[p];
        float4 v = *reinterpret_cast<const float4*>(&g_h1f[(size_t)s * F1 + f4 * 4]);
        acc.x += w * v.x; acc.y += w * v.y; acc.z += w * v.z; acc.w += w * v.w;
    }
    size_t o = (size_t)node * F1 + f4 * 4;
    float a[4] = {acc.x, acc.y, acc.z, acc.w};
#pragma unroll
    for (int i = 0; i < 4; i++) split2(a[i], g_a2h[o + i], g_a2l[o + i]);
}

// ================= tensor-core dual GEMM, cp.async 2-stage pipeline =================
// C = relu(A1@B1^T + A2@B2^T + bias), split hi/lo bf16 (3 mma passes).
// 128x128 tile, 8 warps (2x4), K-chunk 64, double-buffered SMEM stages.
#define CHK 64
#define PAD 72                       // bf16 row pitch (conflict-free ldmatrix)
#define ARR_BYTES (128 * PAD * 2)    // 18432
#define STG_BYTES (4 * ARR_BYTES)    // 73728 (Ah, Al, Bh, Bl)
#define SMEM_BYTES (2 * STG_BYTES)   // 147456

__global__ __launch_bounds__(256) void k_gemm_tc(
    const __nv_bfloat16* __restrict__ A1h, const __nv_bfloat16* __restrict__ A1l,
    const __nv_bfloat16* __restrict__ B1h, const __nv_bfloat16* __restrict__ B1l,
    const __nv_bfloat16* __restrict__ A2h, const __nv_bfloat16* __restrict__ A2l,
    const __nv_bfloat16* __restrict__ B2h, const __nv_bfloat16* __restrict__ B2l,
    int K, const float* __restrict__ bias,
    float* __restrict__ Cf, __nv_bfloat16* __restrict__ Ch, __nv_bfloat16* __restrict__ Cl,
    int M, int Nc) {
    extern __shared__ char smem[];
    uint32_t sb = smem_u32(smem);
    int tid = threadIdx.x;
    int wid = tid >> 5, lane = tid & 31;
    int warpM = wid >> 2, warpN = wid & 3;   // 2 x 4
    int m0 = blockIdx.y * 128, n0 = blockIdx.x * 128;

    float acc[4][4][4];
#pragma unroll
    for (int i = 0; i < 4; i++)
#pragma unroll
        for (int j = 0; j < 4; j++)
#pragma unroll
            for (int q = 0; q < 4; q++) acc[i][j][q] = 0.f;

    int ncpp = K / CHK;
    int NC = 2 * ncpp;

    // per-thread ldmatrix base offsets (bytes, within a stage)
    uint32_t a_lane = (uint32_t)((lane & 15) * PAD + (lane >> 4) * 8) * 2;
    uint32_t b_lane = (uint32_t)((lane & 7) * PAD + ((lane >> 3) & 1) * 8) * 2;

    // issue cp.async loads for chunk c into stage stg
    auto issue = [&](int c, int stg) {
        int ph = c / ncpp;
        int kk = (c % ncpp) * CHK;
        const __nv_bfloat16* arr0 = ph ? A2h : A1h;
        const __nv_bfloat16* arr1 = ph ? A2l : A1l;
        const __nv_bfloat16* arr2 = ph ? B2h : B1h;
        const __nv_bfloat16* arr3 = ph ? B2l : B1l;
        uint32_t sdst = sb + (uint32_t)stg * STG_BYTES;
#pragma unroll
        for (int i = 0; i < 16; i++) {
            int unit = i * 256 + tid;          // 0..4095
            int arr = unit >> 10;              // 0..3
            int rem = unit & 1023;
            int row = rem >> 3, cg = rem & 7;  // 128 rows x 8 col-groups (8 bf16 each)
            uint32_t dst = sdst + (uint32_t)arr * ARR_BYTES + (uint32_t)(row * PAD + cg * 8) * 2;
            if (arr < 2) {
                const __nv_bfloat16* base = (arr == 0) ? arr0 : arr1;
                int m = m0 + row;
                uint32_t sz = (m < M) ? 16u : 0u;
                int mc = (m < M) ? m : 0;
                cpa16(dst, base + (size_t)mc * K + kk + cg * 8, sz);
            } else {
                const __nv_bfloat16* base = (arr == 2) ? arr2 : arr3;
                cpa16(dst, base + (size_t)(n0 + row) * K + kk + cg * 8, 16u);
            }
        }
    };

    issue(0, 0);
    cp_commit();

    for (int c = 0; c < NC; c++) {
        if (c + 1 < NC) { issue(c + 1, (c + 1) & 1); cp_commit(); }
        if (c + 1 < NC) cp_wait<1>(); else cp_wait<0>();
        __syncthreads();

        uint32_t sst = sb + (uint32_t)(c & 1) * STG_BYTES;
        uint32_t aH = sst + a_lane, aL = sst + ARR_BYTES + a_lane;
        uint32_t bH = sst + 2 * ARR_BYTES + b_lane, bL = sst + 3 * ARR_BYTES + b_lane;

#pragma unroll
        for (int ks = 0; ks < CHK / 16; ks++) {
            uint32_t bh[4][2], bl[4][2];
#pragma unroll
            for (int nt = 0; nt < 4; nt++) {
                uint32_t off = (uint32_t)((warpN * 32 + nt * 8) * PAD + ks * 16) * 2;
                ldm_x2(bh[nt], bH + off);
                ldm_x2(bl[nt], bL + off);
            }
#pragma unroll
            for (int mt = 0; mt < 4; mt++) {
                uint32_t ah[4], al[4];
                uint32_t off = (uint32_t)((warpM * 64 + mt * 16) * PAD + ks * 16) * 2;
                ldm_x4(ah, aH + off);
                ldm_x4(al, aL + off);
#pragma unroll
                for (int nt = 0; nt < 4; nt++) {
                    mma_bf16(acc[mt][nt], ah, bh[nt]);
                    mma_bf16(acc[mt][nt], ah, bl[nt]);
                    mma_bf16(acc[mt][nt], al, bh[nt]);
                }
            }
        }
        __syncthreads();   // protect stage (c&1) before it is refilled at iter c+2
    }

    // epilogue: bias + relu (+ optional hi/lo split for next layer)
#pragma unroll
    for (int mt = 0; mt < 4; mt++) {
#pragma unroll
        for (int nt = 0; nt < 4; nt++) {
            int n = n0 + warpN * 32 + nt * 8 + (lane & 3) * 2;
            float b0 = __ldg(&bias[n]), b1v = __ldg(&bias[n + 1]);
#pragma unroll
            for (int h = 0; h < 2; h++) {
                int m = m0 + warpM * 64 + mt * 16 + (lane >> 2) + h * 8;
                if (m < M) {
                    size_t o = (size_t)m * Nc + n;
                    float v0 = fmaxf(acc[mt][nt][h * 2 + 0] + b0, 0.f);
                    float v1 = fmaxf(acc[mt][nt][h * 2 + 1] + b1v, 0.f);
                    Cf[o] = v0; Cf[o + 1] = v1;
                    if (Ch) {
                        split2(v0, Ch[o], Cl[o]);
                        split2(v1, Ch[o + 1], Cl[o + 1]);
                    }
                }
            }
        }
    }
}

// ================= pooling + MLP head =================
__global__ void k_bounds(const int* __restrict__ batch) {
    int g = threadIdx.x;
    if (g > NG) return;
    int lo = 0, hi = NN;
    while (lo < hi) { int mid = (lo + hi) >> 1; if (batch[mid] < g) lo = mid + 1; else hi = mid; }
    g_start[g] = lo;
}
__global__ void k_pool() {
    int g = blockIdx.x >> 2;
    int f = ((blockIdx.x & 3) << 7) + threadIdx.x;
    int s0 = g_start[g], s1 = g_start[g + 1];
    float acc = 0.f;
    for (int n = s0; n < s1; n++) acc += g_h2f[(size_t)n * F1 + f];
    g_gv[g * F1 + f] = acc / fmaxf((float)(s1 - s0), 1.0f);
}
__global__ void k_mlp(const float* __restrict__ Wl1, const float* __restrict__ bl1,
                      const float* __restrict__ Wl2, const float* __restrict__ bl2,
                      const float* __restrict__ Wl3, const float* __restrict__ bl3,
                      float* __restrict__ out) {
    int g = blockIdx.x, t = threadIdx.x;
    __shared__ float gv[F1], t1[64], t2[16];
    for (int i = t; i < F1; i += 64) gv[i] = g_gv[g * F1 + i];
    __syncthreads();
    float a = bl1[t];
    for (int k = 0; k < F1; k++) a += gv[k] * Wl1[k * 64 + t];
    t1[t] = fmaxf(a, 0.f);
    __syncthreads();
    if (t < 16) {
        float a2 = bl2[t];
        for (int k = 0; k < 64; k++) a2 += t1[k] * Wl2[k * 16 + t];
        t2[t] = fmaxf(a2, 0.f);
    }
    __syncthreads();
    if (t == 0) {
        float a3 = bl3[0];
        for (int k = 0; k < 16; k++) a3 += t2[k] * Wl3[k];
        out[g] = a3;
    }
}

// ================= launch =================
extern "C" void kernel_launch(void* const* d_in, const int* in_sizes, int n_in,
                              void* d_out, int out_size) {
    const float* x       = (const float*)d_in[0];
    const int*   ei      = (const int*)d_in[1];
    const float* ea      = (const float*)d_in[2];
    const int*   batch   = (const int*)d_in[3];
    const float* W1_rel  = (const float*)d_in[4];
    const float* b1      = (const float*)d_in[5];
    const float* W1_root = (const float*)d_in[6];
    const float* W2_rel  = (const float*)d_in[7];
    const float* b2      = (const float*)d_in[8];
    const float* W2_root = (const float*)d_in[9];
    const float* Wl1     = (const float*)d_in[10];
    const float* bl1     = (const float*)d_in[11];
    const float* Wl2     = (const float*)d_in[12];
    const float* bl2     = (const float*)d_in[13];
    const float* Wl3     = (const float*)d_in[14];
    const float* bl3     = (const float*)d_in[15];
    float* out = (float*)d_out;

    cudaFuncSetAttribute(k_gemm_tc, cudaFuncAttributeMaxDynamicSharedMemorySize, SMEM_BYTES);

#define SYM(T, p, s) T* p; cudaGetSymbolAddress((void**)&p, s)
    SYM(__nv_bfloat16, xh, g_xh);   SYM(__nv_bfloat16, xl, g_xl);
    SYM(__nv_bfloat16, a1h, g_a1h); SYM(__nv_bfloat16, a1l, g_a1l);
    SYM(float, h1f, g_h1f);
    SYM(__nv_bfloat16, h1h, g_h1h); SYM(__nv_bfloat16, h1l, g_h1l);
    SYM(__nv_bfloat16, a2h, g_a2h); SYM(__nv_bfloat16, a2l, g_a2l);
    SYM(float, h2f, g_h2f);
    SYM(__nv_bfloat16, w1rh, g_w1rh); SYM(__nv_bfloat16, w1rl, g_w1rl);
    SYM(__nv_bfloat16, w1th, g_w1th); SYM(__nv_bfloat16, w1tl, g_w1tl);
    SYM(__nv_bfloat16, w2rh, g_w2rh); SYM(__nv_bfloat16, w2rl, g_w2rl);
    SYM(__nv_bfloat16, w2th, g_w2th); SYM(__nv_bfloat16, w2tl, g_w2tl);
#undef SYM

    // CSR build
    k_zero_counts<<<(NN + 255) / 256, 256>>>();
    k_hist<<<(NE + 255) / 256, 256>>>(ei);
    k_scan<<<1, 1024>>>();
    k_scatter<<<(NE + 255) / 256, 256>>>(ei, ea);

    // precision splits (x + transposed weights)
    k_split_x<<<(NN * F0 + 255) / 256, 256>>>(x);
    k_split_wT<<<(F0 * F1 + 255) / 256, 256>>>(W1_rel, w1rh, w1rl, F0, F1);
    k_split_wT<<<(F0 * F1 + 255) / 256, 256>>>(W1_root, w1th, w1tl, F0, F1);
    k_split_wT<<<(F1 * F1 + 255) / 256, 256>>>(W2_rel, w2rh, w2rl, F1, F1);
    k_split_wT<<<(F1 * F1 + 255) / 256, 256>>>(W2_root, w2th, w2tl, F1, F1);

    // layer 1: h1 = relu(agg1@W1_rel + x@W1_root + b1)
    k_agg128<<<(NN + 3) / 4, 128>>>(x);
    {
        dim3 grid(F1 / 128, (NN + 127) / 128);
        k_gemm_tc<<<grid, 256, SMEM_BYTES>>>(a1h, a1l, w1rh, w1rl, xh, xl, w1th, w1tl,
                                             F0, b1, h1f, h1h, h1l, NN, F1);
    }
    // layer 2: h2 = relu(agg2@W2_rel + h1@W2_root + b2)
    k_agg512<<<NN, 128>>>();
    {
        dim3 grid(F1 / 128, (NN + 127) / 128);
        k_gemm_tc<<<grid, 256, SMEM_BYTES>>>(a2h, a2l, w2rh, w2rl, h1h, h1l, w2th, w2tl,
                                             F1, b2, h2f, ((__nv_bfloat16*)0), ((__nv_bfloat16*)0),
                                             NN, F1);
    }
    // pool + head
    k_bounds<<<1, NG + 1>>>(batch);
    k_pool<<<NG * 4, 128>>>();
    k_mlp<<<NG, 64>>>(Wl1, bl1, Wl2, bl2, Wl3, bl3, out);
    (void)in_sizes; (void)n_in; (void)out_size;
}

// round 6
// speedup vs baseline: 2.2843x; 1.3002x over previous
#include <cuda_runtime.h>
#include <cuda_fp16.h>
#include <cstdint>

#define NN 25000
#define NE 400000
#define NG 64
#define F0 128
#define F1 512

// ================= device scratch (no allocs allowed) =================
__device__ __half g_x16[NN * F0];          // x in fp16
__device__ __half g_a1[NN * F0];           // agg1 in fp16
__device__ float  g_h1f[NN * F1];          // h1 fp32 (for agg512)
__device__ __half g_h116[NN * F1];         // h1 fp16 (GEMM2 A)
__device__ __half g_a2[NN * F1];           // agg2 fp16
__device__ float  g_h2f[NN * F1];
__device__ __half g_w1rh[F1 * F0], g_w1rl[F1 * F0];  // W1_rel^T  hi/lo
__device__ __half g_w1th[F1 * F0], g_w1tl[F1 * F0];  // W1_root^T hi/lo
__device__ __half g_w2rh[F1 * F1], g_w2rl[F1 * F1];  // W2_rel^T  hi/lo
__device__ __half g_w2th[F1 * F1], g_w2tl[F1 * F1];  // W2_root^T hi/lo
__device__ int   g_deg[NN], g_cursor[NN], g_rowptr[NN + 1], g_srcs[NE];
__device__ float g_wgts[NE];
__device__ int   g_start[NG + 1];
__device__ float g_gv[NG * F1];

// ================= helpers =================
__device__ __forceinline__ uint32_t smem_u32(const void* p) {
    uint32_t a;
    asm("{ .reg .u64 t; cvta.to.shared.u64 t, %1; cvt.u32.u64 %0, t; }" : "=r"(a) : "l"(p));
    return a;
}
__device__ __forceinline__ void ldm_x4(uint32_t* r, uint32_t addr) {
    asm volatile("ldmatrix.sync.aligned.m8n8.x4.shared.b16 {%0,%1,%2,%3}, [%4];"
                 : "=r"(r[0]), "=r"(r[1]), "=r"(r[2]), "=r"(r[3]) : "r"(addr));
}
__device__ __forceinline__ void ldm_x2(uint32_t* r, uint32_t addr) {
    asm volatile("ldmatrix.sync.aligned.m8n8.x2.shared.b16 {%0,%1}, [%2];"
                 : "=r"(r[0]), "=r"(r[1]) : "r"(addr));
}
__device__ __forceinline__ void mma_f16(float* c, const uint32_t* a, const uint32_t* b) {
    asm volatile("mma.sync.aligned.m16n8k16.row.col.f32.f16.f16.f32 "
                 "{%0,%1,%2,%3}, {%4,%5,%6,%7}, {%8,%9}, {%0,%1,%2,%3};"
                 : "+f"(c[0]), "+f"(c[1]), "+f"(c[2]), "+f"(c[3])
                 : "r"(a[0]), "r"(a[1]), "r"(a[2]), "r"(a[3]), "r"(b[0]), "r"(b[1]));
}
__device__ __forceinline__ void cpa16(uint32_t dst, const __half* src, uint32_t sz) {
    asm volatile("cp.async.cg.shared.global [%0], [%1], 16, %2;"
                 :: "r"(dst), "l"(__cvta_generic_to_global(src)), "r"(sz) : "memory");
}
__device__ __forceinline__ void cp_commit() {
    asm volatile("cp.async.commit_group;" ::: "memory");
}
template <int N>
__device__ __forceinline__ void cp_wait() {
    asm volatile("cp.async.wait_group %0;" :: "n"(N) : "memory");
}
__device__ __forceinline__ void split2h(float v, __half& h, __half& l) {
    h = __float2half_rn(v);
    l = __float2half_rn(v - __half2float(h));
}

// ================= CSR build =================
__global__ void k_zero_counts() {
    int i = blockIdx.x * blockDim.x + threadIdx.x;
    if (i < NN) { g_deg[i] = 0; g_cursor[i] = 0; }
}
__global__ void k_hist(const int* __restrict__ ei) {
    int e = blockIdx.x * blockDim.x + threadIdx.x;
    if (e < NE) atomicAdd(&g_deg[ei[NE + e]], 1);
}
__global__ void k_scan() {
    __shared__ int s[1024];
    const int CH = (NN + 1023) / 1024;
    int t = threadIdx.x, base = t * CH, sum = 0;
    for (int i = 0; i < CH; i++) { int idx = base + i; sum += (idx < NN) ? g_deg[idx] : 0; }
    s[t] = sum; __syncthreads();
    for (int off = 1; off < 1024; off <<= 1) {
        int v = (t >= off) ? s[t - off] : 0; __syncthreads();
        s[t] += v; __syncthreads();
    }
    int run = (t == 0) ? 0 : s[t - 1];
    for (int i = 0; i < CH; i++) {
        int idx = base + i;
        if (idx < NN) { g_rowptr[idx] = run; run += g_deg[idx]; }
    }
    if (t == 1023) g_rowptr[NN] = s[1023];
}
__global__ void k_scatter(const int* __restrict__ ei, const float* __restrict__ ea) {
    int e = blockIdx.x * blockDim.x + threadIdx.x;
    if (e >= NE) return;
    int src = ei[e], dst = ei[NE + e];
    int pos = g_rowptr[dst] + atomicAdd(&g_cursor[dst], 1);
    g_srcs[pos] = src; g_wgts[pos] = ea[e];
}

// ================= conversions =================
__global__ void k_conv_x(const float* __restrict__ x) {
    int i = blockIdx.x * blockDim.x + threadIdx.x;
    if (i < NN * F0) g_x16[i] = __float2half_rn(x[i]);
}
__global__ void k_split_wT(const float* __restrict__ W, __half* __restrict__ th,
                           __half* __restrict__ tl, int K, int N) {
    int i = blockIdx.x * blockDim.x + threadIdx.x;
    if (i >= K * N) return;
    int k = i / N, n = i % N;
    split2h(W[i], th[n * K + k], tl[n * K + k]);
}

// ================= aggregation (gather-side, atomic-free) =================
__global__ void k_agg128(const float* __restrict__ x) {
    int node = blockIdx.x * 4 + (threadIdx.x >> 5);
    if (node >= NN) return;
    int lane = threadIdx.x & 31;
    int beg = g_rowptr[node], end = g_rowptr[node + 1];
    float4 acc = make_float4(0.f, 0.f, 0.f, 0.f);
    for (int p = beg; p < end; p++) {
        int s = g_srcs[p]; float w = g_wgts[p];
        float4 v = *reinterpret_cast<const float4*>(&x[s * F0 + lane * 4]);
        acc.x += w * v.x; acc.y += w * v.y; acc.z += w * v.z; acc.w += w * v.w;
    }
    int o = node * F0 + lane * 4;
    g_a1[o + 0] = __float2half_rn(acc.x);
    g_a1[o + 1] = __float2half_rn(acc.y);
    g_a1[o + 2] = __float2half_rn(acc.z);
    g_a1[o + 3] = __float2half_rn(acc.w);
}
__global__ void k_agg512() {
    int node = blockIdx.x, f4 = threadIdx.x;
    int beg = g_rowptr[node], end = g_rowptr[node + 1];
    float4 acc = make_float4(0.f, 0.f, 0.f, 0.f);
    for (int p = beg; p < end; p++) {
        int s = g_srcs[p]; float w = g_wgts[p];
        float4 v = *reinterpret_cast<const float4*>(&g_h1f[(size_t)s * F1 + f4 * 4]);
        acc.x += w * v.x; acc.y += w * v.y; acc.z += w * v.z; acc.w += w * v.w;
    }
    size_t o = (size_t)node * F1 + f4 * 4;
    g_a2[o + 0] = __float2half_rn(acc.x);
    g_a2[o + 1] = __float2half_rn(acc.y);
    g_a2[o + 2] = __float2half_rn(acc.z);
    g_a2[o + 3] = __float2half_rn(acc.w);
}

// ================= tensor-core dual GEMM, fp16 2-pass, cp.async pipeline =================
// C = relu(A1@B1^T + A2@B2^T + bias). A fp16, B^T split hi/lo fp16 (2 mma passes).
// 128x128 tile, 8 warps (2x4), K-chunk 64, double-buffered SMEM stages.
#define CHK 64
#define PAD 72                       // fp16 row pitch (conflict-free ldmatrix)
#define ARR_BYTES (128 * PAD * 2)    // 18432
#define STG_BYTES (3 * ARR_BYTES)    // 55296 (A, Bh, Bl)
#define SMEM_BYTES (2 * STG_BYTES)   // 110592

__global__ __launch_bounds__(256) void k_gemm_tc(
    const __half* __restrict__ A1, const __half* __restrict__ B1h, const __half* __restrict__ B1l,
    const __half* __restrict__ A2, const __half* __restrict__ B2h, const __half* __restrict__ B2l,
    int K, const float* __restrict__ bias,
    float* __restrict__ Cf, __half* __restrict__ C16,
    int M, int Nc) {
    extern __shared__ char smem[];
    uint32_t sb = smem_u32(smem);
    int tid = threadIdx.x;
    int wid = tid >> 5, lane = tid & 31;
    int warpM = wid >> 2, warpN = wid & 3;   // 2 x 4
    int m0 = blockIdx.y * 128, n0 = blockIdx.x * 128;

    float acc[4][4][4];
#pragma unroll
    for (int i = 0; i < 4; i++)
#pragma unroll
        for (int j = 0; j < 4; j++)
#pragma unroll
            for (int q = 0; q < 4; q++) acc[i][j][q] = 0.f;

    int ncpp = K / CHK;
    int NC = 2 * ncpp;

    uint32_t a_lane = (uint32_t)((lane & 15) * PAD + (lane >> 4) * 8) * 2;
    uint32_t b_lane = (uint32_t)((lane & 7) * PAD + ((lane >> 3) & 1) * 8) * 2;

    // issue cp.async loads for chunk c into stage stg: arrays {A, Bh, Bl}
    auto issue = [&](int c, int stg) {
        int ph = c / ncpp;
        int kk = (c % ncpp) * CHK;
        const __half* arr0 = ph ? A2 : A1;
        const __half* arr1 = ph ? B2h : B1h;
        const __half* arr2 = ph ? B2l : B1l;
        uint32_t sdst = sb + (uint32_t)stg * STG_BYTES;
#pragma unroll
        for (int i = 0; i < 12; i++) {
            int unit = i * 256 + tid;          // 0..3071
            int arr = unit >> 10;              // 0..2
            int rem = unit & 1023;
            int row = rem >> 3, cg = rem & 7;  // 128 rows x 8 col-groups (8 halves)
            uint32_t dst = sdst + (uint32_t)arr * ARR_BYTES + (uint32_t)(row * PAD + cg * 8) * 2;
            if (arr == 0) {
                int m = m0 + row;
                uint32_t sz = (m < M) ? 16u : 0u;
                int mc = (m < M) ? m : 0;
                cpa16(dst, arr0 + (size_t)mc * K + kk + cg * 8, sz);
            } else {
                const __half* base = (arr == 1) ? arr1 : arr2;
                cpa16(dst, base + (size_t)(n0 + row) * K + kk + cg * 8, 16u);
            }
        }
    };

    issue(0, 0);
    cp_commit();

    for (int c = 0; c < NC; c++) {
        if (c + 1 < NC) { issue(c + 1, (c + 1) & 1); cp_commit(); }
        if (c + 1 < NC) cp_wait<1>(); else cp_wait<0>();
        __syncthreads();

        uint32_t sst = sb + (uint32_t)(c & 1) * STG_BYTES;
        uint32_t aA = sst + a_lane;
        uint32_t bH = sst + ARR_BYTES + b_lane, bL = sst + 2 * ARR_BYTES + b_lane;

#pragma unroll
        for (int ks = 0; ks < CHK / 16; ks++) {
            uint32_t bh[4][2], bl[4][2];
#pragma unroll
            for (int nt = 0; nt < 4; nt++) {
                uint32_t off = (uint32_t)((warpN * 32 + nt * 8) * PAD + ks * 16) * 2;
                ldm_x2(bh[nt], bH + off);
                ldm_x2(bl[nt], bL + off);
            }
#pragma unroll
            for (int mt = 0; mt < 4; mt++) {
                uint32_t av[4];
                uint32_t off = (uint32_t)((warpM * 64 + mt * 16) * PAD + ks * 16) * 2;
                ldm_x4(av, aA + off);
#pragma unroll
                for (int nt = 0; nt < 4; nt++) {
                    mma_f16(acc[mt][nt], av, bh[nt]);
                    mma_f16(acc[mt][nt], av, bl[nt]);
                }
            }
        }
        __syncthreads();   // protect stage (c&1) before refill at iter c+2
    }

    // epilogue: bias + relu (+ optional fp16 copy for next layer's A)
#pragma unroll
    for (int mt = 0; mt < 4; mt++) {
#pragma unroll
        for (int nt = 0; nt < 4; nt++) {
            int n = n0 + warpN * 32 + nt * 8 + (lane & 3) * 2;
            float b0 = __ldg(&bias[n]), b1v = __ldg(&bias[n + 1]);
#pragma unroll
            for (int h = 0; h < 2; h++) {
                int m = m0 + warpM * 64 + mt * 16 + (lane >> 2) + h * 8;
                if (m < M) {
                    size_t o = (size_t)m * Nc + n;
                    float v0 = fmaxf(acc[mt][nt][h * 2 + 0] + b0, 0.f);
                    float v1 = fmaxf(acc[mt][nt][h * 2 + 1] + b1v, 0.f);
                    Cf[o] = v0; Cf[o + 1] = v1;
                    if (C16) {
                        C16[o] = __float2half_rn(v0);
                        C16[o + 1] = __float2half_rn(v1);
                    }
                }
            }
        }
    }
}

// ================= pooling + MLP head =================
__global__ void k_bounds(const int* __restrict__ batch) {
    int g = threadIdx.x;
    if (g > NG) return;
    int lo = 0, hi = NN;
    while (lo < hi) { int mid = (lo + hi) >> 1; if (batch[mid] < g) lo = mid + 1; else hi = mid; }
    g_start[g] = lo;
}
__global__ void k_pool() {
    int g = blockIdx.x >> 2;
    int f = ((blockIdx.x & 3) << 7) + threadIdx.x;
    int s0 = g_start[g], s1 = g_start[g + 1];
    float acc = 0.f;
    for (int n = s0; n < s1; n++) acc += g_h2f[(size_t)n * F1 + f];
    g_gv[g * F1 + f] = acc / fmaxf((float)(s1 - s0), 1.0f);
}
__global__ void k_mlp(const float* __restrict__ Wl1, const float* __restrict__ bl1,
                      const float* __restrict__ Wl2, const float* __restrict__ bl2,
                      const float* __restrict__ Wl3, const float* __restrict__ bl3,
                      float* __restrict__ out) {
    int g = blockIdx.x, t = threadIdx.x;
    __shared__ float gv[F1], t1[64], t2[16];
    for (int i = t; i < F1; i += 64) gv[i] = g_gv[g * F1 + i];
    __syncthreads();
    float a = bl1[t];
    for (int k = 0; k < F1; k++) a += gv[k] * Wl1[k * 64 + t];
    t1[t] = fmaxf(a, 0.f);
    __syncthreads();
    if (t < 16) {
        float a2 = bl2[t];
        for (int k = 0; k < 64; k++) a2 += t1[k] * Wl2[k * 16 + t];
        t2[t] = fmaxf(a2, 0.f);
    }
    __syncthreads();
    if (t == 0) {
        float a3 = bl3[0];
        for (int k = 0; k < 16; k++) a3 += t2[k] * Wl3[k];
        out[g] = a3;
    }
}

// ================= launch =================
extern "C" void kernel_launch(void* const* d_in, const int* in_sizes, int n_in,
                              void* d_out, int out_size) {
    const float* x       = (const float*)d_in[0];
    const int*   ei      = (const int*)d_in[1];
    const float* ea      = (const float*)d_in[2];
    const int*   batch   = (const int*)d_in[3];
    const float* W1_rel  = (const float*)d_in[4];
    const float* b1      = (const float*)d_in[5];
    const float* W1_root = (const float*)d_in[6];
    const float* W2_rel  = (const float*)d_in[7];
    const float* b2      = (const float*)d_in[8];
    const float* W2_root = (const float*)d_in[9];
    const float* Wl1     = (const float*)d_in[10];
    const float* bl1     = (const float*)d_in[11];
    const float* Wl2     = (const float*)d_in[12];
    const float* bl2     = (const float*)d_in[13];
    const float* Wl3     = (const float*)d_in[14];
    const float* bl3     = (const float*)d_in[15];
    float* out = (float*)d_out;

    cudaFuncSetAttribute(k_gemm_tc, cudaFuncAttributeMaxDynamicSharedMemorySize, SMEM_BYTES);

#define SYM(T, p, s) T* p; cudaGetSymbolAddress((void**)&p, s)
    SYM(__half, x16, g_x16);   SYM(__half, a1, g_a1);
    SYM(float, h1f, g_h1f);    SYM(__half, h116, g_h116);
    SYM(__half, a2, g_a2);     SYM(float, h2f, g_h2f);
    SYM(__half, w1rh, g_w1rh); SYM(__half, w1rl, g_w1rl);
    SYM(__half, w1th, g_w1th); SYM(__half, w1tl, g_w1tl);
    SYM(__half, w2rh, g_w2rh); SYM(__half, w2rl, g_w2rl);
    SYM(__half, w2th, g_w2th); SYM(__half, w2tl, g_w2tl);
#undef SYM

    // CSR build
    k_zero_counts<<<(NN + 255) / 256, 256>>>();
    k_hist<<<(NE + 255) / 256, 256>>>(ei);
    k_scan<<<1, 1024>>>();
    k_scatter<<<(NE + 255) / 256, 256>>>(ei, ea);

    // conversions (x fp16 + transposed hi/lo weights)
    k_conv_x<<<(NN * F0 + 255) / 256, 256>>>(x);
    k_split_wT<<<(F0 * F1 + 255) / 256, 256>>>(W1_rel, w1rh, w1rl, F0, F1);
    k_split_wT<<<(F0 * F1 + 255) / 256, 256>>>(W1_root, w1th, w1tl, F0, F1);
    k_split_wT<<<(F1 * F1 + 255) / 256, 256>>>(W2_rel, w2rh, w2rl, F1, F1);
    k_split_wT<<<(F1 * F1 + 255) / 256, 256>>>(W2_root, w2th, w2tl, F1, F1);

    // layer 1: h1 = relu(agg1@W1_rel + x@W1_root + b1)
    k_agg128<<<(NN + 3) / 4, 128>>>(x);
    {
        dim3 grid(F1 / 128, (NN + 127) / 128);
        k_gemm_tc<<<grid, 256, SMEM_BYTES>>>(a1, w1rh, w1rl, x16, w1th, w1tl,
                                             F0, b1, h1f, h116, NN, F1);
    }
    // layer 2: h2 = relu(agg2@W2_rel + h1@W2_root + b2)
    k_agg512<<<NN, 128>>>();
    {
        dim3 grid(F1 / 128, (NN + 127) / 128);
        k_gemm_tc<<<grid, 256, SMEM_BYTES>>>(a2, w2rh, w2rl, h116, w2th, w2tl,
                                             F1, b2, h2f, ((__half*)0), NN, F1);
    }
    // pool + head
    k_bounds<<<1, NG + 1>>>(batch);
    k_pool<<<NG * 4, 128>>>();
    k_mlp<<<NG, 64>>>(Wl1, bl1, Wl2, bl2, Wl3, bl3, out);
    (void)in_sizes; (void)n_in; (void)out_size;
}

// round 8
// speedup vs baseline: 2.4588x; 1.0764x over previous
#include <cuda_runtime.h>
#include <cuda_fp16.h>
#include <cstdint>

#define NN 25000
#define NE 400000
#define NG 64
#define F0 128
#define F1 512

// ================= device scratch (no allocs allowed) =================
__device__ __half g_x16[NN * F0];          // x in fp16
__device__ __half g_a1[NN * F0];           // agg1 fp16
__device__ __half g_h116[NN * F1];         // h1 fp16 (GEMM2 A + agg512 src)
__device__ __half g_a2[NN * F1];           // agg2 fp16
__device__ float  g_h2f[NN * F1];          // h2 fp32 (pool src)
__device__ __half g_w1rh[F1 * F0], g_w1rl[F1 * F0];  // W1_rel^T  hi/lo
__device__ __half g_w1th[F1 * F0], g_w1tl[F1 * F0];  // W1_root^T hi/lo
__device__ __half g_w2rh[F1 * F1], g_w2rl[F1 * F1];  // W2_rel^T  hi/lo
__device__ __half g_w2th[F1 * F1], g_w2tl[F1 * F1];  // W2_root^T hi/lo
__device__ int   g_deg[NN], g_cursor[NN], g_rowptr[NN + 1], g_srcs[NE];
__device__ float g_wgts[NE];
__device__ int   g_start[NG + 1];
__device__ float g_gv[NG * F1];

// ================= helpers =================
__device__ __forceinline__ uint32_t smem_u32(const void* p) {
    uint32_t a;
    asm("{ .reg .u64 t; cvta.to.shared.u64 t, %1; cvt.u32.u64 %0, t; }" : "=r"(a) : "l"(p));
    return a;
}
__device__ __forceinline__ void ldm_x4(uint32_t* r, uint32_t addr) {
    asm volatile("ldmatrix.sync.aligned.m8n8.x4.shared.b16 {%0,%1,%2,%3}, [%4];"
                 : "=r"(r[0]), "=r"(r[1]), "=r"(r[2]), "=r"(r[3]) : "r"(addr));
}
__device__ __forceinline__ void ldm_x2(uint32_t* r, uint32_t addr) {
    asm volatile("ldmatrix.sync.aligned.m8n8.x2.shared.b16 {%0,%1}, [%2];"
                 : "=r"(r[0]), "=r"(r[1]) : "r"(addr));
}
__device__ __forceinline__ void mma_f16(float* c, const uint32_t* a, const uint32_t* b) {
    asm volatile("mma.sync.aligned.m16n8k16.row.col.f32.f16.f16.f32 "
                 "{%0,%1,%2,%3}, {%4,%5,%6,%7}, {%8,%9}, {%0,%1,%2,%3};"
                 : "+f"(c[0]), "+f"(c[1]), "+f"(c[2]), "+f"(c[3])
                 : "r"(a[0]), "r"(a[1]), "r"(a[2]), "r"(a[3]), "r"(b[0]), "r"(b[1]));
}
__device__ __forceinline__ void cpa16(uint32_t dst, const __half* src, uint32_t sz) {
    asm volatile("cp.async.cg.shared.global [%0], [%1], 16, %2;"
                 :: "r"(dst), "l"(__cvta_generic_to_global(src)), "r"(sz) : "memory");
}
__device__ __forceinline__ void cp_commit() {
    asm volatile("cp.async.commit_group;" ::: "memory");
}
template <int N>
__device__ __forceinline__ void cp_wait() {
    asm volatile("cp.async.wait_group %0;" :: "n"(N) : "memory");
}
__device__ __forceinline__ void split2h(float v, __half& h, __half& l) {
    h = __float2half_rn(v);
    l = __float2half_rn(v - __half2float(h));
}

// ================= CSR build =================
__global__ void k_zero_counts() {
    int i = blockIdx.x * blockDim.x + threadIdx.x;
    if (i < NN) { g_deg[i] = 0; g_cursor[i] = 0; }
}
__global__ void k_hist(const int* __restrict__ ei) {
    int e = blockIdx.x * blockDim.x + threadIdx.x;
    if (e < NE) atomicAdd(&g_deg[ei[NE + e]], 1);
}
__global__ void k_scan() {
    __shared__ int s[1024];
    const int CH = (NN + 1023) / 1024;
    int t = threadIdx.x, base = t * CH, sum = 0;
    for (int i = 0; i < CH; i++) { int idx = base + i; sum += (idx < NN) ? g_deg[idx] : 0; }
    s[t] = sum; __syncthreads();
    for (int off = 1; off < 1024; off <<= 1) {
        int v = (t >= off) ? s[t - off] : 0; __syncthreads();
        s[t] += v; __syncthreads();
    }
    int run = (t == 0) ? 0 : s[t - 1];
    for (int i = 0; i < CH; i++) {
        int idx = base + i;
        if (idx < NN) { g_rowptr[idx] = run; run += g_deg[idx]; }
    }
    if (t == 1023) g_rowptr[NN] = s[1023];
}
__global__ void k_scatter(const int* __restrict__ ei, const float* __restrict__ ea) {
    int e = blockIdx.x * blockDim.x + threadIdx.x;
    if (e >= NE) return;
    int src = ei[e], dst = ei[NE + e];
    int pos = g_rowptr[dst] + atomicAdd(&g_cursor[dst], 1);
    g_srcs[pos] = src; g_wgts[pos] = ea[e];
}

// ================= conversions =================
__global__ void k_conv_x(const float* __restrict__ x) {
    int i = blockIdx.x * blockDim.x + threadIdx.x;
    if (i < NN * F0) g_x16[i] = __float2half_rn(x[i]);
}
__global__ void k_split_wT(const float* __restrict__ W, __half* __restrict__ th,
                           __half* __restrict__ tl, int K, int N) {
    int i = blockIdx.x * blockDim.x + threadIdx.x;
    if (i >= K * N) return;
    int k = i / N, n = i % N;
    split2h(W[i], th[n * K + k], tl[n * K + k]);
}

// ================= aggregation (gather-side, atomic-free) =================
__global__ void k_agg128(const float* __restrict__ x) {
    int node = blockIdx.x * 4 + (threadIdx.x >> 5);
    if (node >= NN) return;
    int lane = threadIdx.x & 31;
    int beg = g_rowptr[node], end = g_rowptr[node + 1];
    float4 acc = make_float4(0.f, 0.f, 0.f, 0.f);
    for (int p = beg; p < end; p++) {
        int s = g_srcs[p]; float w = g_wgts[p];
        float4 v = *reinterpret_cast<const float4*>(&x[s * F0 + lane * 4]);
        acc.x += w * v.x; acc.y += w * v.y; acc.z += w * v.z; acc.w += w * v.w;
    }
    int o = node * F0 + lane * 4;
    g_a1[o + 0] = __float2half_rn(acc.x);
    g_a1[o + 1] = __float2half_rn(acc.y);
    g_a1[o + 2] = __float2half_rn(acc.z);
    g_a1[o + 3] = __float2half_rn(acc.w);
}
// gather h1 in fp16 (halved traffic vs fp32); accumulate fp32
__global__ void k_agg512() {
    int node = blockIdx.x, f4 = threadIdx.x;  // 128 threads, 4 halves each
    int beg = g_rowptr[node], end = g_rowptr[node + 1];
    float acc0 = 0.f, acc1 = 0.f, acc2 = 0.f, acc3 = 0.f;
    for (int p = beg; p < end; p++) {
        int s = g_srcs[p]; float w = g_wgts[p];
        uint2 raw = *reinterpret_cast<const uint2*>(&g_h116[(size_t)s * F1 + f4 * 4]);
        __half2 v01 = *reinterpret_cast<__half2*>(&raw.x);
        __half2 v23 = *reinterpret_cast<__half2*>(&raw.y);
        float2 f01 = __half22float2(v01), f23 = __half22float2(v23);
        acc0 += w * f01.x; acc1 += w * f01.y; acc2 += w * f23.x; acc3 += w * f23.y;
    }
    size_t o = (size_t)node * F1 + f4 * 4;
    g_a2[o + 0] = __float2half_rn(acc0);
    g_a2[o + 1] = __float2half_rn(acc1);
    g_a2[o + 2] = __float2half_rn(acc2);
    g_a2[o + 3] = __float2half_rn(acc3);
}

// ================= tensor-core dual GEMM, fp16 A + split-weight B (2 passes) =================
// C = relu(A1@B1^T + A2@B2^T + bias). A fp16, B^T split hi/lo fp16.
// 128x128 tile, 8 warps (2x4), K-chunk 64, double-buffered stages {A, Bh, Bl}.
#define CHK 64
#define PAD 72                       // fp16 row pitch (conflict-free ldmatrix)
#define ARR_BYTES (128 * PAD * 2)    // 18432
#define STG_BYTES (3 * ARR_BYTES)    // 55296 (A, Bh, Bl)
#define SMEM_BYTES (2 * STG_BYTES)   // 110592

__global__ __launch_bounds__(256) void k_gemm_tc(
    const __half* __restrict__ A1, const __half* __restrict__ B1h, const __half* __restrict__ B1l,
    const __half* __restrict__ A2, const __half* __restrict__ B2h, const __half* __restrict__ B2l,
    int K, const float* __restrict__ bias,
    float* __restrict__ Cf, __half* __restrict__ C16,
    int M, int Nc) {
    extern __shared__ char smem[];
    uint32_t sb = smem_u32(smem);
    int tid = threadIdx.x;
    int wid = tid >> 5, lane = tid & 31;
    int warpM = wid >> 2, warpN = wid & 3;   // 2 x 4
    int m0 = blockIdx.y * 128, n0 = blockIdx.x * 128;

    float acc[4][4][4];
#pragma unroll
    for (int i = 0; i < 4; i++)
#pragma unroll
        for (int j = 0; j < 4; j++)
#pragma unroll
            for (int q = 0; q < 4; q++) acc[i][j][q] = 0.f;

    int ncpp = K / CHK;
    int NC = 2 * ncpp;

    uint32_t a_lane = (uint32_t)((lane & 15) * PAD + (lane >> 4) * 8) * 2;
    uint32_t b_lane = (uint32_t)((lane & 7) * PAD + ((lane >> 3) & 1) * 8) * 2;

    // cp.async chunk c -> stage stg: arrays {A, Bh, Bl}
    auto issue = [&](int c, int stg) {
        int ph = c / ncpp;
        int kk = (c % ncpp) * CHK;
        const __half* arr0 = ph ? A2 : A1;
        const __half* arr1 = ph ? B2h : B1h;
        const __half* arr2 = ph ? B2l : B1l;
        uint32_t sdst = sb + (uint32_t)stg * STG_BYTES;
#pragma unroll
        for (int i = 0; i < 12; i++) {
            int unit = i * 256 + tid;          // 0..3071
            int arr = unit >> 10;              // 0..2
            int rem = unit & 1023;
            int row = rem >> 3, cg = rem & 7;  // 128 rows x 8 col-groups (8 halves)
            uint32_t dst = sdst + (uint32_t)arr * ARR_BYTES + (uint32_t)(row * PAD + cg * 8) * 2;
            if (arr == 0) {
                int m = m0 + row;
                uint32_t sz = (m < M) ? 16u : 0u;
                int mc = (m < M) ? m : 0;
                cpa16(dst, arr0 + (size_t)mc * K + kk + cg * 8, sz);
            } else {
                const __half* base = (arr == 1) ? arr1 : arr2;
                cpa16(dst, base + (size_t)(n0 + row) * K + kk + cg * 8, 16u);
            }
        }
    };

    issue(0, 0);
    cp_commit();

    for (int c = 0; c < NC; c++) {
        if (c + 1 < NC) { issue(c + 1, (c + 1) & 1); cp_commit(); }
        if (c + 1 < NC) cp_wait<1>(); else cp_wait<0>();
        __syncthreads();

        uint32_t sst = sb + (uint32_t)(c & 1) * STG_BYTES;
        uint32_t aA = sst + a_lane;
        uint32_t bH = sst + ARR_BYTES + b_lane, bL = sst + 2 * ARR_BYTES + b_lane;

#pragma unroll
        for (int ks = 0; ks < CHK / 16; ks++) {
            uint32_t bh[4][2], bl[4][2];
#pragma unroll
            for (int nt = 0; nt < 4; nt++) {
                uint32_t off = (uint32_t)((warpN * 32 + nt * 8) * PAD + ks * 16) * 2;
                ldm_x2(bh[nt], bH + off);
                ldm_x2(bl[nt], bL + off);
            }
#pragma unroll
            for (int mt = 0; mt < 4; mt++) {
                uint32_t av[4];
                uint32_t off = (uint32_t)((warpM * 64 + mt * 16) * PAD + ks * 16) * 2;
                ldm_x4(av, aA + off);
#pragma unroll
                for (int nt = 0; nt < 4; nt++) {
                    mma_f16(acc[mt][nt], av, bh[nt]);
                    mma_f16(acc[mt][nt], av, bl[nt]);
                }
            }
        }
        __syncthreads();   // protect stage (c&1) before refill at iter c+2
    }

    // epilogue: bias + relu; write fp32 (if Cf) and/or fp16 (if C16)
#pragma unroll
    for (int mt = 0; mt < 4; mt++) {
#pragma unroll
        for (int nt = 0; nt < 4; nt++) {
            int n = n0 + warpN * 32 + nt * 8 + (lane & 3) * 2;
            float b0 = __ldg(&bias[n]), b1v = __ldg(&bias[n + 1]);
#pragma unroll
            for (int h = 0; h < 2; h++) {
                int m = m0 + warpM * 64 + mt * 16 + (lane >> 2) + h * 8;
                if (m < M) {
                    size_t o = (size_t)m * Nc + n;
                    float v0 = fmaxf(acc[mt][nt][h * 2 + 0] + b0, 0.f);
                    float v1 = fmaxf(acc[mt][nt][h * 2 + 1] + b1v, 0.f);
                    if (Cf) { Cf[o] = v0; Cf[o + 1] = v1; }
                    if (C16) {
                        C16[o] = __float2half_rn(v0);
                        C16[o + 1] = __float2half_rn(v1);
                    }
                }
            }
        }
    }
}

// ================= pooling + MLP head =================
__global__ void k_bounds(const int* __restrict__ batch) {
    int g = threadIdx.x;
    if (g > NG) return;
    int lo = 0, hi = NN;
    while (lo < hi) { int mid = (lo + hi) >> 1; if (batch[mid] < g) lo = mid + 1; else hi = mid; }
    g_start[g] = lo;
}
__global__ void k_pool() {
    int g = blockIdx.x >> 2;
    int f = ((blockIdx.x & 3) << 7) + threadIdx.x;
    int s0 = g_start[g], s1 = g_start[g + 1];
    float acc = 0.f;
    for (int n = s0; n < s1; n++) acc += g_h2f[(size_t)n * F1 + f];
    g_gv[g * F1 + f] = acc / fmaxf((float)(s1 - s0), 1.0f);
}
__global__ void k_mlp(const float* __restrict__ Wl1, const float* __restrict__ bl1,
                      const float* __restrict__ Wl2, const float* __restrict__ bl2,
                      const float* __restrict__ Wl3, const float* __restrict__ bl3,
                      float* __restrict__ out) {
    int g = blockIdx.x, t = threadIdx.x;
    __shared__ float gv[F1], t1[64], t2[16];
    for (int i = t; i < F1; i += 64) gv[i] = g_gv[g * F1 + i];
    __syncthreads();
    float a = bl1[t];
    for (int k = 0; k < F1; k++) a += gv[k] * Wl1[k * 64 + t];
    t1[t] = fmaxf(a, 0.f);
    __syncthreads();
    if (t < 16) {
        float a2 = bl2[t];
        for (int k = 0; k < 64; k++) a2 += t1[k] * Wl2[k * 16 + t];
        t2[t] = fmaxf(a2, 0.f);
    }
    __syncthreads();
    if (t == 0) {
        float a3 = bl3[0];
        for (int k = 0; k < 16; k++) a3 += t2[k] * Wl3[k];
        out[g] = a3;
    }
}

// ================= launch =================
extern "C" void kernel_launch(void* const* d_in, const int* in_sizes, int n_in,
                              void* d_out, int out_size) {
    const float* x       = (const float*)d_in[0];
    const int*   ei      = (const int*)d_in[1];
    const float* ea      = (const float*)d_in[2];
    const int*   batch   = (const int*)d_in[3];
    const float* W1_rel  = (const float*)d_in[4];
    const float* b1      = (const float*)d_in[5];
    const float* W1_root = (const float*)d_in[6];
    const float* W2_rel  = (const float*)d_in[7];
    const float* b2      = (const float*)d_in[8];
    const float* W2_root = (const float*)d_in[9];
    const float* Wl1     = (const float*)d_in[10];
    const float* bl1     = (const float*)d_in[11];
    const float* Wl2     = (const float*)d_in[12];
    const float* bl2     = (const float*)d_in[13];
    const float* Wl3     = (const float*)d_in[14];
    const float* bl3     = (const float*)d_in[15];
    float* out = (float*)d_out;

    cudaFuncSetAttribute(k_gemm_tc, cudaFuncAttributeMaxDynamicSharedMemorySize, SMEM_BYTES);

#define SYM(T, p, s) T* p; cudaGetSymbolAddress((void**)&p, s)
    SYM(__half, x16, g_x16);  SYM(__half, a1, g_a1);
    SYM(__half, h116, g_h116);
    SYM(__half, a2, g_a2);    SYM(float, h2f, g_h2f);
    SYM(__half, w1rh, g_w1rh); SYM(__half, w1rl, g_w1rl);
    SYM(__half, w1th, g_w1th); SYM(__half, w1tl, g_w1tl);
    SYM(__half, w2rh, g_w2rh); SYM(__half, w2rl, g_w2rl);
    SYM(__half, w2th, g_w2th); SYM(__half, w2tl, g_w2tl);
#undef SYM

    // CSR build
    k_zero_counts<<<(NN + 255) / 256, 256>>>();
    k_hist<<<(NE + 255) / 256, 256>>>(ei);
    k_scan<<<1, 1024>>>();
    k_scatter<<<(NE + 255) / 256, 256>>>(ei, ea);

    // conversions (x fp16 + transposed hi/lo weights)
    k_conv_x<<<(NN * F0 + 255) / 256, 256>>>(x);
    k_split_wT<<<(F0 * F1 + 255) / 256, 256>>>(W1_rel, w1rh, w1rl, F0, F1);
    k_split_wT<<<(F0 * F1 + 255) / 256, 256>>>(W1_root, w1th, w1tl, F0, F1);
    k_split_wT<<<(F1 * F1 + 255) / 256, 256>>>(W2_rel, w2rh, w2rl, F1, F1);
    k_split_wT<<<(F1 * F1 + 255) / 256, 256>>>(W2_root, w2th, w2tl, F1, F1);

    // layer 1: h1(fp16) = relu(agg1@W1_rel + x@W1_root + b1)
    k_agg128<<<(NN + 3) / 4, 128>>>(x);
    {
        dim3 grid(F1 / 128, (NN + 127) / 128);
        k_gemm_tc<<<grid, 256, SMEM_BYTES>>>(a1, w1rh, w1rl, x16, w1th, w1tl,
                                             F0, b1, ((float*)0), h116, NN, F1);
    }
    // layer 2: h2(fp32) = relu(agg2@W2_rel + h1@W2_root + b2)
    k_agg512<<<NN, 128>>>();
    {
        dim3 grid(F1 / 128, (NN + 127) / 128);
        k_gemm_tc<<<grid, 256, SMEM_BYTES>>>(a2, w2rh, w2rl, h116, w2th, w2tl,
                                             F1, b2, h2f, ((__half*)0), NN, F1);
    }
    // pool + head
    k_bounds<<<1, NG + 1>>>(batch);
    k_pool<<<NG * 4, 128>>>();
    k_mlp<<<NG, 64>>>(Wl1, bl1, Wl2, bl2, Wl3, bl3, out);
    (void)in_sizes; (void)n_in; (void)out_size;
}

// round 9
// speedup vs baseline: 2.8498x; 1.1590x over previous
#include <cuda_runtime.h>
#include <cuda_fp16.h>
#include <cstdint>

#define NN 25000
#define NE 400000
#define NG 64
#define F0 128
#define F1 512

// ================= device scratch (no allocs allowed) =================
__device__ __half g_x16[NN * F0];          // x in fp16
__device__ __half g_a1[NN * F0];           // agg1 fp16
__device__ __half g_h116[NN * F1];         // h1 fp16 (GEMM2 A + agg512 src)
__device__ __half g_a2[NN * F1];           // agg2 fp16
__device__ float  g_h2f[NN * F1];          // h2 fp32 (pool src)
__device__ __half g_w1rh[F1 * F0], g_w1rl[F1 * F0];  // W1_rel^T  hi/lo
__device__ __half g_w1th[F1 * F0], g_w1tl[F1 * F0];  // W1_root^T hi/lo
__device__ __half g_w2rh[F1 * F1], g_w2rl[F1 * F1];  // W2_rel^T  hi/lo
__device__ __half g_w2th[F1 * F1], g_w2tl[F1 * F1];  // W2_root^T hi/lo
__device__ int   g_deg[NN], g_cursor[NN], g_rowptr[NN + 1], g_srcs[NE];
__device__ float g_wgts[NE];
__device__ float g_gv[NG * F1];

// ================= helpers =================
__device__ __forceinline__ uint32_t smem_u32(const void* p) {
    uint32_t a;
    asm("{ .reg .u64 t; cvta.to.shared.u64 t, %1; cvt.u32.u64 %0, t; }" : "=r"(a) : "l"(p));
    return a;
}
__device__ __forceinline__ void ldm_x4(uint32_t* r, uint32_t addr) {
    asm volatile("ldmatrix.sync.aligned.m8n8.x4.shared.b16 {%0,%1,%2,%3}, [%4];"
                 : "=r"(r[0]), "=r"(r[1]), "=r"(r[2]), "=r"(r[3]) : "r"(addr));
}
__device__ __forceinline__ void mma_f16(float* c, const uint32_t* a, const uint32_t* b) {
    asm volatile("mma.sync.aligned.m16n8k16.row.col.f32.f16.f16.f32 "
                 "{%0,%1,%2,%3}, {%4,%5,%6,%7}, {%8,%9}, {%0,%1,%2,%3};"
                 : "+f"(c[0]), "+f"(c[1]), "+f"(c[2]), "+f"(c[3])
                 : "r"(a[0]), "r"(a[1]), "r"(a[2]), "r"(a[3]), "r"(b[0]), "r"(b[1]));
}
__device__ __forceinline__ void cpa16(uint32_t dst, const __half* src, uint32_t sz) {
    asm volatile("cp.async.cg.shared.global [%0], [%1], 16, %2;"
                 :: "r"(dst), "l"(__cvta_generic_to_global(src)), "r"(sz) : "memory");
}
__device__ __forceinline__ void cp_commit() {
    asm volatile("cp.async.commit_group;" ::: "memory");
}
template <int N>
__device__ __forceinline__ void cp_wait() {
    asm volatile("cp.async.wait_group %0;" :: "n"(N) : "memory");
}
__device__ __forceinline__ void split2h(float v, __half& h, __half& l) {
    h = __float2half_rn(v);
    l = __float2half_rn(v - __half2float(h));
}

// ================= CSR build =================
__global__ void k_zero_counts() {
    int i = blockIdx.x * blockDim.x + threadIdx.x;
    if (i < NN) { g_deg[i] = 0; g_cursor[i] = 0; }
}
__global__ void k_hist(const int* __restrict__ ei) {
    int e = blockIdx.x * blockDim.x + threadIdx.x;
    if (e < NE) atomicAdd(&g_deg[ei[NE + e]], 1);
}
__global__ void k_scan() {
    __shared__ int s[1024];
    const int CH = (NN + 1023) / 1024;
    int t = threadIdx.x, base = t * CH, sum = 0;
    for (int i = 0; i < CH; i++) { int idx = base + i; sum += (idx < NN) ? g_deg[idx] : 0; }
    s[t] = sum; __syncthreads();
    for (int off = 1; off < 1024; off <<= 1) {
        int v = (t >= off) ? s[t - off] : 0; __syncthreads();
        s[t] += v; __syncthreads();
    }
    int run = (t == 0) ? 0 : s[t - 1];
    for (int i = 0; i < CH; i++) {
        int idx = base + i;
        if (idx < NN) { g_rowptr[idx] = run; run += g_deg[idx]; }
    }
    if (t == 1023) g_rowptr[NN] = s[1023];
}
__global__ void k_scatter(const int* __restrict__ ei, const float* __restrict__ ea) {
    int e = blockIdx.x * blockDim.x + threadIdx.x;
    if (e >= NE) return;
    int src = ei[e], dst = ei[NE + e];
    int pos = g_rowptr[dst] + atomicAdd(&g_cursor[dst], 1);
    g_srcs[pos] = src; g_wgts[pos] = ea[e];
}

// ================= fused weight split (all 4 transposed hi/lo weights) =================
#define W1_ELEMS (F0 * F1)   // 65536
#define W2_ELEMS (F1 * F1)   // 262144
__global__ void k_split_all(const float* __restrict__ W1_rel, const float* __restrict__ W1_root,
                            const float* __restrict__ W2_rel, const float* __restrict__ W2_root) {
    int i = blockIdx.x * blockDim.x + threadIdx.x;
    const float* W; __half* th; __half* tl; int K, idx;
    if (i < W1_ELEMS) {
        W = W1_rel; th = g_w1rh; tl = g_w1rl; K = F0; idx = i;
    } else if (i < 2 * W1_ELEMS) {
        W = W1_root; th = g_w1th; tl = g_w1tl; K = F0; idx = i - W1_ELEMS;
    } else if (i < 2 * W1_ELEMS + W2_ELEMS) {
        W = W2_rel; th = g_w2rh; tl = g_w2rl; K = F1; idx = i - 2 * W1_ELEMS;
    } else if (i < 2 * W1_ELEMS + 2 * W2_ELEMS) {
        W = W2_root; th = g_w2th; tl = g_w2tl; K = F1; idx = i - 2 * W1_ELEMS - W2_ELEMS;
    } else return;
    int k = idx / F1, n = idx % F1;   // all weights are [K, 512]
    split2h(W[idx], th[n * K + k], tl[n * K + k]);
}

// ================= aggregation (gather-side, atomic-free) =================
// also converts this node's own x-row to fp16 (folds k_conv_x)
__global__ void k_agg128(const float* __restrict__ x) {
    int node = blockIdx.x * 4 + (threadIdx.x >> 5);
    if (node >= NN) return;
    int lane = threadIdx.x & 31;
    int o = node * F0 + lane * 4;
    // own-row fp16 conversion (root term input)
    {
        float4 v = *reinterpret_cast<const float4*>(&x[o]);
        g_x16[o + 0] = __float2half_rn(v.x);
        g_x16[o + 1] = __float2half_rn(v.y);
        g_x16[o + 2] = __float2half_rn(v.z);
        g_x16[o + 3] = __float2half_rn(v.w);
    }
    int beg = g_rowptr[node], end = g_rowptr[node + 1];
    float4 acc = make_float4(0.f, 0.f, 0.f, 0.f);
    for (int p = beg; p < end; p++) {
        int s = g_srcs[p]; float w = g_wgts[p];
        float4 v = *reinterpret_cast<const float4*>(&x[s * F0 + lane * 4]);
        acc.x += w * v.x; acc.y += w * v.y; acc.z += w * v.z; acc.w += w * v.w;
    }
    g_a1[o + 0] = __float2half_rn(acc.x);
    g_a1[o + 1] = __float2half_rn(acc.y);
    g_a1[o + 2] = __float2half_rn(acc.z);
    g_a1[o + 3] = __float2half_rn(acc.w);
}
// gather h1 in fp16; accumulate fp32
__global__ void k_agg512() {
    int node = blockIdx.x, f4 = threadIdx.x;  // 128 threads, 4 halves each
    int beg = g_rowptr[node], end = g_rowptr[node + 1];
    float acc0 = 0.f, acc1 = 0.f, acc2 = 0.f, acc3 = 0.f;
    for (int p = beg; p < end; p++) {
        int s = g_srcs[p]; float w = g_wgts[p];
        uint2 raw = *reinterpret_cast<const uint2*>(&g_h116[(size_t)s * F1 + f4 * 4]);
        __half2 v01 = *reinterpret_cast<__half2*>(&raw.x);
        __half2 v23 = *reinterpret_cast<__half2*>(&raw.y);
        float2 f01 = __half22float2(v01), f23 = __half22float2(v23);
        acc0 += w * f01.x; acc1 += w * f01.y; acc2 += w * f23.x; acc3 += w * f23.y;
    }
    size_t o = (size_t)node * F1 + f4 * 4;
    g_a2[o + 0] = __float2half_rn(acc0);
    g_a2[o + 1] = __float2half_rn(acc1);
    g_a2[o + 2] = __float2half_rn(acc2);
    g_a2[o + 3] = __float2half_rn(acc3);
}

// ================= tensor-core dual GEMM, fp16 A + split-weight B (2 passes) =================
#define CHK 64
#define PAD 72                       // fp16 row pitch (conflict-free ldmatrix)
#define ARR_BYTES (128 * PAD * 2)    // 18432
#define STG_BYTES (3 * ARR_BYTES)    // 55296 (A, Bh, Bl)
#define SMEM_BYTES (2 * STG_BYTES)   // 110592

__global__ __launch_bounds__(256) void k_gemm_tc(
    const __half* __restrict__ A1, const __half* __restrict__ B1h, const __half* __restrict__ B1l,
    const __half* __restrict__ A2, const __half* __restrict__ B2h, const __half* __restrict__ B2l,
    int K, const float* __restrict__ bias,
    float* __restrict__ Cf, __half* __restrict__ C16,
    int M, int Nc) {
    extern __shared__ char smem[];
    uint32_t sb = smem_u32(smem);
    int tid = threadIdx.x;
    int wid = tid >> 5, lane = tid & 31;
    int warpM = wid >> 2, warpN = wid & 3;   // 2 x 4
    int m0 = blockIdx.y * 128, n0 = blockIdx.x * 128;

    float acc[4][4][4];
#pragma unroll
    for (int i = 0; i < 4; i++)
#pragma unroll
        for (int j = 0; j < 4; j++)
#pragma unroll
            for (int q = 0; q < 4; q++) acc[i][j][q] = 0.f;

    int ncpp = K / CHK;
    int NC = 2 * ncpp;

    // A ldmatrix x4: rows 0-15 across lanes 0-15, k halves via lane>>4
    uint32_t a_lane = (uint32_t)((lane & 15) * PAD + (lane >> 4) * 8) * 2;
    // B ldmatrix x4 (two n8 frags): bit3 -> k-group, bit4 -> +8 n-rows
    uint32_t b_lane = (uint32_t)(((lane & 7) + ((lane >> 4) << 3)) * PAD
                                 + ((lane >> 3) & 1) * 8) * 2;

    // cp.async chunk c -> stage stg: arrays {A, Bh, Bl}
    auto issue = [&](int c, int stg) {
        int ph = c / ncpp;
        int kk = (c % ncpp) * CHK;
        const __half* arr0 = ph ? A2 : A1;
        const __half* arr1 = ph ? B2h : B1h;
        const __half* arr2 = ph ? B2l : B1l;
        uint32_t sdst = sb + (uint32_t)stg * STG_BYTES;
#pragma unroll
        for (int i = 0; i < 12; i++) {
            int unit = i * 256 + tid;          // 0..3071
            int arr = unit >> 10;              // 0..2
            int rem = unit & 1023;
            int row = rem >> 3, cg = rem & 7;  // 128 rows x 8 col-groups (8 halves)
            uint32_t dst = sdst + (uint32_t)arr * ARR_BYTES + (uint32_t)(row * PAD + cg * 8) * 2;
            if (arr == 0) {
                int m = m0 + row;
                uint32_t sz = (m < M) ? 16u : 0u;
                int mc = (m < M) ? m : 0;
                cpa16(dst, arr0 + (size_t)mc * K + kk + cg * 8, sz);
            } else {
                const __half* base = (arr == 1) ? arr1 : arr2;
                cpa16(dst, base + (size_t)(n0 + row) * K + kk + cg * 8, 16u);
            }
        }
    };

    issue(0, 0);
    cp_commit();

    for (int c = 0; c < NC; c++) {
        if (c + 1 < NC) { issue(c + 1, (c + 1) & 1); cp_commit(); }
        if (c + 1 < NC) cp_wait<1>(); else cp_wait<0>();
        __syncthreads();

        uint32_t sst = sb + (uint32_t)(c & 1) * STG_BYTES;
        uint32_t aA = sst + a_lane;
        uint32_t bH = sst + ARR_BYTES + b_lane, bL = sst + 2 * ARR_BYTES + b_lane;

#pragma unroll
        for (int ks = 0; ks < CHK / 16; ks++) {
            // B frags: 2 x ldm_x4 per array -> four n8 frags each
            uint32_t bh[4][2], bl[4][2];
#pragma unroll
            for (int np = 0; np < 2; np++) {   // nt pairs {0,1}, {2,3}
                uint32_t off = (uint32_t)((warpN * 32 + np * 16) * PAD + ks * 16) * 2;
                uint32_t r4[4];
                ldm_x4(r4, bH + off);
                bh[np * 2][0] = r4[0]; bh[np * 2][1] = r4[1];
                bh[np * 2 + 1][0] = r4[2]; bh[np * 2 + 1][1] = r4[3];
                ldm_x4(r4, bL + off);
                bl[np * 2][0] = r4[0]; bl[np * 2][1] = r4[1];
                bl[np * 2 + 1][0] = r4[2]; bl[np * 2 + 1][1] = r4[3];
            }
#pragma unroll
            for (int mt = 0; mt < 4; mt++) {
                uint32_t av[4];
                uint32_t off = (uint32_t)((warpM * 64 + mt * 16) * PAD + ks * 16) * 2;
                ldm_x4(av, aA + off);
#pragma unroll
                for (int nt = 0; nt < 4; nt++) {
                    mma_f16(acc[mt][nt], av, bh[nt]);
                    mma_f16(acc[mt][nt], av, bl[nt]);
                }
            }
        }
        __syncthreads();   // protect stage (c&1) before refill at iter c+2
    }

    // epilogue: bias + relu; write fp32 (if Cf) and/or fp16 (if C16)
#pragma unroll
    for (int mt = 0; mt < 4; mt++) {
#pragma unroll
        for (int nt = 0; nt < 4; nt++) {
            int n = n0 + warpN * 32 + nt * 8 + (lane & 3) * 2;
            float b0 = __ldg(&bias[n]), b1v = __ldg(&bias[n + 1]);
#pragma unroll
            for (int h = 0; h < 2; h++) {
                int m = m0 + warpM * 64 + mt * 16 + (lane >> 2) + h * 8;
                if (m < M) {
                    size_t o = (size_t)m * Nc + n;
                    float v0 = fmaxf(acc[mt][nt][h * 2 + 0] + b0, 0.f);
                    float v1 = fmaxf(acc[mt][nt][h * 2 + 1] + b1v, 0.f);
                    if (Cf) { Cf[o] = v0; Cf[o + 1] = v1; }
                    if (C16) {
                        C16[o] = __float2half_rn(v0);
                        C16[o + 1] = __float2half_rn(v1);
                    }
                }
            }
        }
    }
}

// ================= pooling (bounds folded in) + MLP head =================
__global__ void k_pool(const int* __restrict__ batch) {
    __shared__ int bounds[2];
    int g = blockIdx.x >> 2;
    int f = ((blockIdx.x & 3) << 7) + threadIdx.x;
    if (threadIdx.x < 2) {
        int target = g + threadIdx.x;
        int lo = 0, hi = NN;
        while (lo < hi) {
            int mid = (lo + hi) >> 1;
            if (batch[mid] < target) lo = mid + 1; else hi = mid;
        }
        bounds[threadIdx.x] = lo;
    }
    __syncthreads();
    int s0 = bounds[0], s1 = bounds[1];
    float acc = 0.f;
    for (int n = s0; n < s1; n++) acc += g_h2f[(size_t)n * F1 + f];
    g_gv[g * F1 + f] = acc / fmaxf((float)(s1 - s0), 1.0f);
}
__global__ void k_mlp(const float* __restrict__ Wl1, const float* __restrict__ bl1,
                      const float* __restrict__ Wl2, const float* __restrict__ bl2,
                      const float* __restrict__ Wl3, const float* __restrict__ bl3,
                      float* __restrict__ out) {
    int g = blockIdx.x, t = threadIdx.x;
    __shared__ float gv[F1], t1[64], t2[16];
    for (int i = t; i < F1; i += 64) gv[i] = g_gv[g * F1 + i];
    __syncthreads();
    float a = bl1[t];
    for (int k = 0; k < F1; k++) a += gv[k] * Wl1[k * 64 + t];
    t1[t] = fmaxf(a, 0.f);
    __syncthreads();
    if (t < 16) {
        float a2 = bl2[t];
        for (int k = 0; k < 64; k++) a2 += t1[k] * Wl2[k * 16 + t];
        t2[t] = fmaxf(a2, 0.f);
    }
    __syncthreads();
    if (t == 0) {
        float a3 = bl3[0];
        for (int k = 0; k < 16; k++) a3 += t2[k] * Wl3[k];
        out[g] = a3;
    }
}

// ================= launch =================
extern "C" void kernel_launch(void* const* d_in, const int* in_sizes, int n_in,
                              void* d_out, int out_size) {
    const float* x       = (const float*)d_in[0];
    const int*   ei      = (const int*)d_in[1];
    const float* ea      = (const float*)d_in[2];
    const int*   batch   = (const int*)d_in[3];
    const float* W1_rel  = (const float*)d_in[4];
    const float* b1      = (const float*)d_in[5];
    const float* W1_root = (const float*)d_in[6];
    const float* W2_rel  = (const float*)d_in[7];
    const float* b2      = (const float*)d_in[8];
    const float* W2_root = (const float*)d_in[9];
    const float* Wl1     = (const float*)d_in[10];
    const float* bl1     = (const float*)d_in[11];
    const float* Wl2     = (const float*)d_in[12];
    const float* bl2     = (const float*)d_in[13];
    const float* Wl3     = (const float*)d_in[14];
    const float* bl3     = (const float*)d_in[15];
    float* out = (float*)d_out;

    cudaFuncSetAttribute(k_gemm_tc, cudaFuncAttributeMaxDynamicSharedMemorySize, SMEM_BYTES);

#define SYM(T, p, s) T* p; cudaGetSymbolAddress((void**)&p, s)
    SYM(__half, x16, g_x16);  SYM(__half, a1, g_a1);
    SYM(__half, h116, g_h116);
    SYM(__half, a2, g_a2);    SYM(float, h2f, g_h2f);
    SYM(__half, w1rh, g_w1rh); SYM(__half, w1rl, g_w1rl);
    SYM(__half, w1th, g_w1th); SYM(__half, w1tl, g_w1tl);
    SYM(__half, w2rh, g_w2rh); SYM(__half, w2rl, g_w2rl);
    SYM(__half, w2th, g_w2th); SYM(__half, w2tl, g_w2tl);
#undef SYM

    // CSR build
    k_zero_counts<<<(NN + 255) / 256, 256>>>();
    k_hist<<<(NE + 255) / 256, 256>>>(ei);
    k_scan<<<1, 1024>>>();
    k_scatter<<<(NE + 255) / 256, 256>>>(ei, ea);

    // fused weight splits (1 launch)
    k_split_all<<<(2 * W1_ELEMS + 2 * W2_ELEMS + 255) / 256, 256>>>(W1_rel, W1_root, W2_rel, W2_root);

    // layer 1: h1(fp16) = relu(agg1@W1_rel + x@W1_root + b1)   (agg128 also emits x16)
    k_agg128<<<(NN + 3) / 4, 128>>>(x);
    {
        dim3 grid(F1 / 128, (NN + 127) / 128);
        k_gemm_tc<<<grid, 256, SMEM_BYTES>>>(a1, w1rh, w1rl, x16, w1th, w1tl,
                                             F0, b1, ((float*)0), h116, NN, F1);
    }
    // layer 2: h2(fp32) = relu(agg2@W2_rel + h1@W2_root + b2)
    k_agg512<<<NN, 128>>>();
    {
        dim3 grid(F1 / 128, (NN + 127) / 128);
        k_gemm_tc<<<grid, 256, SMEM_BYTES>>>(a2, w2rh, w2rl, h116, w2th, w2tl,
                                             F1, b2, h2f, ((__half*)0), NN, F1);
    }
    // pool (+bounds) + head
    k_pool<<<NG * 4, 128>>>(batch);
    k_mlp<<<NG, 64>>>(Wl1, bl1, Wl2, bl2, Wl3, bl3, out);
    (void)in_sizes; (void)n_in; (void)out_size;
}

// round 10
// speedup vs baseline: 2.8628x; 1.0046x over previous
#include <cuda_runtime.h>
#include <cuda_fp16.h>
#include <cstdint>

#define NN 25000
#define NE 400000
#define NG 64
#define F0 128
#define F1 512

// ================= device scratch (no allocs allowed) =================
__device__ __half g_x16[NN * F0];          // x in fp16
__device__ __half g_a1[NN * F0];           // agg1 fp16
__device__ __half g_h116[NN * F1];         // h1 fp16 (GEMM2 A + agg512 src)
__device__ __half g_a2[NN * F1];           // agg2 fp16
__device__ float  g_h2f[NN * F1];          // h2 fp32 (pool src)
__device__ __half g_w1rh[F1 * F0], g_w1rl[F1 * F0];  // W1_rel^T  hi/lo
__device__ __half g_w1th[F1 * F0], g_w1tl[F1 * F0];  // W1_root^T hi/lo
__device__ __half g_w2rh[F1 * F1], g_w2rl[F1 * F1];  // W2_rel^T  hi/lo
__device__ __half g_w2th[F1 * F1], g_w2tl[F1 * F1];  // W2_root^T hi/lo
__device__ int   g_deg[NN], g_cursor[NN], g_rowptr[NN + 1], g_srcs[NE];
__device__ float g_wgts[NE];
__device__ float g_gv[NG * F1];

// ================= helpers =================
__device__ __forceinline__ uint32_t smem_u32(const void* p) {
    uint32_t a;
    asm("{ .reg .u64 t; cvta.to.shared.u64 t, %1; cvt.u32.u64 %0, t; }" : "=r"(a) : "l"(p));
    return a;
}
__device__ __forceinline__ void ldm_x4(uint32_t* r, uint32_t addr) {
    asm volatile("ldmatrix.sync.aligned.m8n8.x4.shared.b16 {%0,%1,%2,%3}, [%4];"
                 : "=r"(r[0]), "=r"(r[1]), "=r"(r[2]), "=r"(r[3]) : "r"(addr));
}
__device__ __forceinline__ void mma_f16(float* c, const uint32_t* a, const uint32_t* b) {
    asm volatile("mma.sync.aligned.m16n8k16.row.col.f32.f16.f16.f32 "
                 "{%0,%1,%2,%3}, {%4,%5,%6,%7}, {%8,%9}, {%0,%1,%2,%3};"
                 : "+f"(c[0]), "+f"(c[1]), "+f"(c[2]), "+f"(c[3])
                 : "r"(a[0]), "r"(a[1]), "r"(a[2]), "r"(a[3]), "r"(b[0]), "r"(b[1]));
}
__device__ __forceinline__ void cpa16(uint32_t dst, const __half* src, uint32_t sz) {
    asm volatile("cp.async.cg.shared.global [%0], [%1], 16, %2;"
                 :: "r"(dst), "l"(__cvta_generic_to_global(src)), "r"(sz) : "memory");
}
__device__ __forceinline__ void cp_commit() {
    asm volatile("cp.async.commit_group;" ::: "memory");
}
template <int N>
__device__ __forceinline__ void cp_wait() {
    asm volatile("cp.async.wait_group %0;" :: "n"(N) : "memory");
}
__device__ __forceinline__ void split2h(float v, __half& h, __half& l) {
    h = __float2half_rn(v);
    l = __float2half_rn(v - __half2float(h));
}

// ================= CSR build =================
__global__ void k_hist(const int* __restrict__ ei) {
    int e = blockIdx.x * blockDim.x + threadIdx.x;
    if (e < NE) atomicAdd(&g_deg[ei[NE + e]], 1);
}
__global__ void k_scan() {
    __shared__ int s[1024];
    const int CH = (NN + 1023) / 1024;
    int t = threadIdx.x, base = t * CH, sum = 0;
    for (int i = 0; i < CH; i++) { int idx = base + i; sum += (idx < NN) ? g_deg[idx] : 0; }
    s[t] = sum; __syncthreads();
    for (int off = 1; off < 1024; off <<= 1) {
        int v = (t >= off) ? s[t - off] : 0; __syncthreads();
        s[t] += v; __syncthreads();
    }
    int run = (t == 0) ? 0 : s[t - 1];
    for (int i = 0; i < CH; i++) {
        int idx = base + i;
        if (idx < NN) { g_rowptr[idx] = run; run += g_deg[idx]; }
    }
    if (t == 1023) g_rowptr[NN] = s[1023];
}
__global__ void k_scatter(const int* __restrict__ ei, const float* __restrict__ ea) {
    int e = blockIdx.x * blockDim.x + threadIdx.x;
    if (e >= NE) return;
    int src = ei[e], dst = ei[NE + e];
    int pos = g_rowptr[dst] + atomicAdd(&g_cursor[dst], 1);
    g_srcs[pos] = src; g_wgts[pos] = ea[e];
}

// ================= fused prep: zero counts + weight splits + x->fp16 =================
#define W1_ELEMS (F0 * F1)   // 65536
#define W2_ELEMS (F1 * F1)   // 262144
#define PREP_W (2 * W1_ELEMS + 2 * W2_ELEMS)           // 655360
#define PREP_Z (PREP_W + NN)                           // +25000
#define PREP_X (PREP_Z + NN * F0)                      // +3200000
__global__ void k_prep(const float* __restrict__ W1_rel, const float* __restrict__ W1_root,
                       const float* __restrict__ W2_rel, const float* __restrict__ W2_root,
                       const float* __restrict__ x) {
    int i = blockIdx.x * blockDim.x + threadIdx.x;
    if (i < PREP_W) {
        const float* W; __half* th; __half* tl; int K, idx;
        if (i < W1_ELEMS) { W = W1_rel; th = g_w1rh; tl = g_w1rl; K = F0; idx = i; }
        else if (i < 2 * W1_ELEMS) { W = W1_root; th = g_w1th; tl = g_w1tl; K = F0; idx = i - W1_ELEMS; }
        else if (i < 2 * W1_ELEMS + W2_ELEMS) { W = W2_rel; th = g_w2rh; tl = g_w2rl; K = F1; idx = i - 2 * W1_ELEMS; }
        else { W = W2_root; th = g_w2th; tl = g_w2tl; K = F1; idx = i - 2 * W1_ELEMS - W2_ELEMS; }
        int k = idx / F1, n = idx % F1;   // all weights are [K, 512]
        split2h(W[idx], th[n * K + k], tl[n * K + k]);
    } else if (i < PREP_Z) {
        int n = i - PREP_W;
        g_deg[n] = 0; g_cursor[n] = 0;
    } else if (i < PREP_X) {
        int n = i - PREP_Z;
        g_x16[n] = __float2half_rn(x[n]);
    }
}

// ================= aggregation (gather-side, atomic-free) =================
// gather x in fp16 (halved traffic); accumulate fp32
__global__ void k_agg128() {
    int node = blockIdx.x * 4 + (threadIdx.x >> 5);
    if (node >= NN) return;
    int lane = threadIdx.x & 31;
    int beg = g_rowptr[node], end = g_rowptr[node + 1];
    float acc0 = 0.f, acc1 = 0.f, acc2 = 0.f, acc3 = 0.f;
    for (int p = beg; p < end; p++) {
        int s = g_srcs[p]; float w = g_wgts[p];
        uint2 raw = *reinterpret_cast<const uint2*>(&g_x16[s * F0 + lane * 4]);
        __half2 v01 = *reinterpret_cast<__half2*>(&raw.x);
        __half2 v23 = *reinterpret_cast<__half2*>(&raw.y);
        float2 f01 = __half22float2(v01), f23 = __half22float2(v23);
        acc0 += w * f01.x; acc1 += w * f01.y; acc2 += w * f23.x; acc3 += w * f23.y;
    }
    int o = node * F0 + lane * 4;
    g_a1[o + 0] = __float2half_rn(acc0);
    g_a1[o + 1] = __float2half_rn(acc1);
    g_a1[o + 2] = __float2half_rn(acc2);
    g_a1[o + 3] = __float2half_rn(acc3);
}
// gather h1 in fp16; accumulate fp32
__global__ void k_agg512() {
    int node = blockIdx.x, f4 = threadIdx.x;  // 128 threads, 4 halves each
    int beg = g_rowptr[node], end = g_rowptr[node + 1];
    float acc0 = 0.f, acc1 = 0.f, acc2 = 0.f, acc3 = 0.f;
    for (int p = beg; p < end; p++) {
        int s = g_srcs[p]; float w = g_wgts[p];
        uint2 raw = *reinterpret_cast<const uint2*>(&g_h116[(size_t)s * F1 + f4 * 4]);
        __half2 v01 = *reinterpret_cast<__half2*>(&raw.x);
        __half2 v23 = *reinterpret_cast<__half2*>(&raw.y);
        float2 f01 = __half22float2(v01), f23 = __half22float2(v23);
        acc0 += w * f01.x; acc1 += w * f01.y; acc2 += w * f23.x; acc3 += w * f23.y;
    }
    size_t o = (size_t)node * F1 + f4 * 4;
    g_a2[o + 0] = __float2half_rn(acc0);
    g_a2[o + 1] = __float2half_rn(acc1);
    g_a2[o + 2] = __float2half_rn(acc2);
    g_a2[o + 3] = __float2half_rn(acc3);
}

// ================= tensor-core dual GEMM, fp16 A + split-weight B (2 passes) =================
#define CHK 64
#define PAD 72                       // fp16 row pitch (conflict-free ldmatrix)
#define ARR_BYTES (128 * PAD * 2)    // 18432
#define STG_BYTES (3 * ARR_BYTES)    // 55296 (A, Bh, Bl)
#define SMEM_BYTES (2 * STG_BYTES)   // 110592

__global__ __launch_bounds__(256) void k_gemm_tc(
    const __half* __restrict__ A1, const __half* __restrict__ B1h, const __half* __restrict__ B1l,
    const __half* __restrict__ A2, const __half* __restrict__ B2h, const __half* __restrict__ B2l,
    int K, const float* __restrict__ bias,
    float* __restrict__ Cf, __half* __restrict__ C16,
    int M, int Nc) {
    extern __shared__ char smem[];
    uint32_t sb = smem_u32(smem);
    int tid = threadIdx.x;
    int wid = tid >> 5, lane = tid & 31;
    int warpM = wid >> 2, warpN = wid & 3;   // 2 x 4
    int m0 = blockIdx.y * 128, n0 = blockIdx.x * 128;

    float acc[4][4][4];
#pragma unroll
    for (int i = 0; i < 4; i++)
#pragma unroll
        for (int j = 0; j < 4; j++)
#pragma unroll
            for (int q = 0; q < 4; q++) acc[i][j][q] = 0.f;

    int ncpp = K / CHK;
    int NC = 2 * ncpp;

    // A ldmatrix x4: rows 0-15 across lanes 0-15, k halves via lane>>4
    uint32_t a_lane = (uint32_t)((lane & 15) * PAD + (lane >> 4) * 8) * 2;
    // B ldmatrix x4 (two n8 frags): bit3 -> k-group, bit4 -> +8 n-rows
    uint32_t b_lane = (uint32_t)(((lane & 7) + ((lane >> 4) << 3)) * PAD
                                 + ((lane >> 3) & 1) * 8) * 2;

    // cp.async chunk c -> stage stg: arrays {A, Bh, Bl}
    auto issue = [&](int c, int stg) {
        int ph = c / ncpp;
        int kk = (c % ncpp) * CHK;
        const __half* arr0 = ph ? A2 : A1;
        const __half* arr1 = ph ? B2h : B1h;
        const __half* arr2 = ph ? B2l : B1l;
        uint32_t sdst = sb + (uint32_t)stg * STG_BYTES;
#pragma unroll
        for (int i = 0; i < 12; i++) {
            int unit = i * 256 + tid;          // 0..3071
            int arr = unit >> 10;              // 0..2
            int rem = unit & 1023;
            int row = rem >> 3, cg = rem & 7;  // 128 rows x 8 col-groups (8 halves)
            uint32_t dst = sdst + (uint32_t)arr * ARR_BYTES + (uint32_t)(row * PAD + cg * 8) * 2;
            if (arr == 0) {
                int m = m0 + row;
                uint32_t sz = (m < M) ? 16u : 0u;
                int mc = (m < M) ? m : 0;
                cpa16(dst, arr0 + (size_t)mc * K + kk + cg * 8, sz);
            } else {
                const __half* base = (arr == 1) ? arr1 : arr2;
                cpa16(dst, base + (size_t)(n0 + row) * K + kk + cg * 8, 16u);
            }
        }
    };

    issue(0, 0);
    cp_commit();

    for (int c = 0; c < NC; c++) {
        cp_wait<0>();        // chunk c's loads arrived
        __syncthreads();     // all warps done consuming chunk c-1 -> its stage is free
        if (c + 1 < NC) { issue(c + 1, (c + 1) & 1); cp_commit(); }

        uint32_t sst = sb + (uint32_t)(c & 1) * STG_BYTES;
        uint32_t aA = sst + a_lane;
        uint32_t bH = sst + ARR_BYTES + b_lane, bL = sst + 2 * ARR_BYTES + b_lane;

#pragma unroll
        for (int ks = 0; ks < CHK / 16; ks++) {
            // B frags: 2 x ldm_x4 per array -> four n8 frags each
            uint32_t bh[4][2], bl[4][2];
#pragma unroll
            for (int np = 0; np < 2; np++) {   // nt pairs {0,1}, {2,3}
                uint32_t off = (uint32_t)((warpN * 32 + np * 16) * PAD + ks * 16) * 2;
                uint32_t r4[4];
                ldm_x4(r4, bH + off);
                bh[np * 2][0] = r4[0]; bh[np * 2][1] = r4[1];
                bh[np * 2 + 1][0] = r4[2]; bh[np * 2 + 1][1] = r4[3];
                ldm_x4(r4, bL + off);
                bl[np * 2][0] = r4[0]; bl[np * 2][1] = r4[1];
                bl[np * 2 + 1][0] = r4[2]; bl[np * 2 + 1][1] = r4[3];
            }
#pragma unroll
            for (int mt = 0; mt < 4; mt++) {
                uint32_t av[4];
                uint32_t off = (uint32_t)((warpM * 64 + mt * 16) * PAD + ks * 16) * 2;
                ldm_x4(av, aA + off);
#pragma unroll
                for (int nt = 0; nt < 4; nt++) {
                    mma_f16(acc[mt][nt], av, bh[nt]);
                    mma_f16(acc[mt][nt], av, bl[nt]);
                }
            }
        }
    }

    // epilogue: bias + relu; write fp32 (if Cf) and/or fp16 (if C16)
#pragma unroll
    for (int mt = 0; mt < 4; mt++) {
#pragma unroll
        for (int nt = 0; nt < 4; nt++) {
            int n = n0 + warpN * 32 + nt * 8 + (lane & 3) * 2;
            float b0 = __ldg(&bias[n]), b1v = __ldg(&bias[n + 1]);
#pragma unroll
            for (int h = 0; h < 2; h++) {
                int m = m0 + warpM * 64 + mt * 16 + (lane >> 2) + h * 8;
                if (m < M) {
                    size_t o = (size_t)m * Nc + n;
                    float v0 = fmaxf(acc[mt][nt][h * 2 + 0] + b0, 0.f);
                    float v1 = fmaxf(acc[mt][nt][h * 2 + 1] + b1v, 0.f);
                    if (Cf) { Cf[o] = v0; Cf[o + 1] = v1; }
                    if (C16) {
                        C16[o] = __float2half_rn(v0);
                        C16[o + 1] = __float2half_rn(v1);
                    }
                }
            }
        }
    }
}

// ================= pooling (bounds folded in) + MLP head =================
__global__ void k_pool(const int* __restrict__ batch) {
    __shared__ int bounds[2];
    int g = blockIdx.x >> 2;
    int f = ((blockIdx.x & 3) << 7) + threadIdx.x;
    if (threadIdx.x < 2) {
        int target = g + threadIdx.x;
        int lo = 0, hi = NN;
        while (lo < hi) {
            int mid = (lo + hi) >> 1;
            if (batch[mid] < target) lo = mid + 1; else hi = mid;
        }
        bounds[threadIdx.x] = lo;
    }
    __syncthreads();
    int s0 = bounds[0], s1 = bounds[1];
    float acc = 0.f;
    for (int n = s0; n < s1; n++) acc += g_h2f[(size_t)n * F1 + f];
    g_gv[g * F1 + f] = acc / fmaxf((float)(s1 - s0), 1.0f);
}
__global__ void k_mlp(const float* __restrict__ Wl1, const float* __restrict__ bl1,
                      const float* __restrict__ Wl2, const float* __restrict__ bl2,
                      const float* __restrict__ Wl3, const float* __restrict__ bl3,
                      float* __restrict__ out) {
    int g = blockIdx.x, t = threadIdx.x;
    __shared__ float gv[F1], t1[64], t2[16];
    for (int i = t; i < F1; i += 64) gv[i] = g_gv[g * F1 + i];
    __syncthreads();
    float a = bl1[t];
    for (int k = 0; k < F1; k++) a += gv[k] * Wl1[k * 64 + t];
    t1[t] = fmaxf(a, 0.f);
    __syncthreads();
    if (t < 16) {
        float a2 = bl2[t];
        for (int k = 0; k < 64; k++) a2 += t1[k] * Wl2[k * 16 + t];
        t2[t] = fmaxf(a2, 0.f);
    }
    __syncthreads();
    if (t == 0) {
        float a3 = bl3[0];
        for (int k = 0; k < 16; k++) a3 += t2[k] * Wl3[k];
        out[g] = a3;
    }
}

// ================= launch =================
extern "C" void kernel_launch(void* const* d_in, const int* in_sizes, int n_in,
                              void* d_out, int out_size) {
    const float* x       = (const float*)d_in[0];
    const int*   ei      = (const int*)d_in[1];
    const float* ea      = (const float*)d_in[2];
    const int*   batch   = (const int*)d_in[3];
    const float* W1_rel  = (const float*)d_in[4];
    const float* b1      = (const float*)d_in[5];
    const float* W1_root = (const float*)d_in[6];
    const float* W2_rel  = (const float*)d_in[7];
    const float* b2      = (const float*)d_in[8];
    const float* W2_root = (const float*)d_in[9];
    const float* Wl1     = (const float*)d_in[10];
    const float* bl1     = (const float*)d_in[11];
    const float* Wl2     = (const float*)d_in[12];
    const float* bl2     = (const float*)d_in[13];
    const float* Wl3     = (const float*)d_in[14];
    const float* bl3     = (const float*)d_in[15];
    float* out = (float*)d_out;

    cudaFuncSetAttribute(k_gemm_tc, cudaFuncAttributeMaxDynamicSharedMemorySize, SMEM_BYTES);

#define SYM(T, p, s) T* p; cudaGetSymbolAddress((void**)&p, s)
    SYM(__half, x16, g_x16);  SYM(__half, a1, g_a1);
    SYM(__half, h116, g_h116);
    SYM(__half, a2, g_a2);    SYM(float, h2f, g_h2f);
    SYM(__half, w1rh, g_w1rh); SYM(__half, w1rl, g_w1rl);
    SYM(__half, w1th, g_w1th); SYM(__half, w1tl, g_w1tl);
    SYM(__half, w2rh, g_w2rh); SYM(__half, w2rl, g_w2rl);
    SYM(__half, w2th, g_w2th); SYM(__half, w2tl, g_w2tl);
#undef SYM

    // prep (zero counts + weight splits + x->fp16) runs while nothing depends on it yet
    k_prep<<<(PREP_X + 255) / 256, 256>>>(W1_rel, W1_root, W2_rel, W2_root, x);

    // CSR build (depends on zeroed counts from k_prep)
    k_hist<<<(NE + 255) / 256, 256>>>(ei);
    k_scan<<<1, 1024>>>();
    k_scatter<<<(NE + 255) / 256, 256>>>(ei, ea);

    // layer 1: h1(fp16) = relu(agg1@W1_rel + x@W1_root + b1)
    k_agg128<<<(NN + 3) / 4, 128>>>();
    {
        dim3 grid(F1 / 128, (NN + 127) / 128);
        k_gemm_tc<<<grid, 256, SMEM_BYTES>>>(a1, w1rh, w1rl, x16, w1th, w1tl,
                                             F0, b1, ((float*)0), h116, NN, F1);
    }
    // layer 2: h2(fp32) = relu(agg2@W2_rel + h1@W2_root + b2)
    k_agg512<<<NN, 128>>>();
    {
        dim3 grid(F1 / 128, (NN + 127) / 128);
        k_gemm_tc<<<grid, 256, SMEM_BYTES>>>(a2, w2rh, w2rl, h116, w2th, w2tl,
                                             F1, b2, h2f, ((__half*)0), NN, F1);
    }
    // pool (+bounds) + head
    k_pool<<<NG * 4, 128>>>(batch);
    k_mlp<<<NG, 64>>>(Wl1, bl1, Wl2, bl2, Wl3, bl3, out);
    (void)in_sizes; (void)n_in; (void)out_size;
}

// round 11
// speedup vs baseline: 3.0742x; 1.0739x over previous
#include <cuda_runtime.h>
#include <cuda_fp16.h>
#include <cstdint>

#define NN 25000
#define NE 400000
#define NG 64
#define F0 128
#define F1 512

// ================= device scratch (no allocs allowed) =================
__device__ __half g_x16[NN * F0];          // x in fp16
__device__ __half g_a1[NN * F0];           // agg1 fp16
__device__ __half g_h116[NN * F1];         // h1 fp16 (GEMM2 A + agg512 src)
__device__ __half g_a2[NN * F1];           // agg2 fp16
__device__ __half g_h216[NN * F1];         // h2 fp16 (pool src)
__device__ __half g_w1rh[F1 * F0], g_w1rl[F1 * F0];  // W1_rel^T  hi/lo
__device__ __half g_w1th[F1 * F0], g_w1tl[F1 * F0];  // W1_root^T hi/lo
__device__ __half g_w2rh[F1 * F1], g_w2rl[F1 * F1];  // W2_rel^T  hi/lo
__device__ __half g_w2th[F1 * F1], g_w2tl[F1 * F1];  // W2_root^T hi/lo
__device__ int   g_deg[NN], g_cursor[NN], g_rowptr[NN + 1], g_srcs[NE];
__device__ float g_wgts[NE];
__device__ float g_gv[NG * F1];

// ================= helpers =================
__device__ __forceinline__ uint32_t smem_u32(const void* p) {
    uint32_t a;
    asm("{ .reg .u64 t; cvta.to.shared.u64 t, %1; cvt.u32.u64 %0, t; }" : "=r"(a) : "l"(p));
    return a;
}
__device__ __forceinline__ void ldm_x4(uint32_t* r, uint32_t addr) {
    asm volatile("ldmatrix.sync.aligned.m8n8.x4.shared.b16 {%0,%1,%2,%3}, [%4];"
                 : "=r"(r[0]), "=r"(r[1]), "=r"(r[2]), "=r"(r[3]) : "r"(addr));
}
__device__ __forceinline__ void mma_f16(float* c, const uint32_t* a, const uint32_t* b) {
    asm volatile("mma.sync.aligned.m16n8k16.row.col.f32.f16.f16.f32 "
                 "{%0,%1,%2,%3}, {%4,%5,%6,%7}, {%8,%9}, {%0,%1,%2,%3};"
                 : "+f"(c[0]), "+f"(c[1]), "+f"(c[2]), "+f"(c[3])
                 : "r"(a[0]), "r"(a[1]), "r"(a[2]), "r"(a[3]), "r"(b[0]), "r"(b[1]));
}
__device__ __forceinline__ void cpa16(uint32_t dst, const __half* src, uint32_t sz) {
    asm volatile("cp.async.cg.shared.global [%0], [%1], 16, %2;"
                 :: "r"(dst), "l"(__cvta_generic_to_global(src)), "r"(sz) : "memory");
}
__device__ __forceinline__ void cp_commit() {
    asm volatile("cp.async.commit_group;" ::: "memory");
}
template <int N>
__device__ __forceinline__ void cp_wait() {
    asm volatile("cp.async.wait_group %0;" :: "n"(N) : "memory");
}
__device__ __forceinline__ void split2h(float v, __half& h, __half& l) {
    h = __float2half_rn(v);
    l = __float2half_rn(v - __half2float(h));
}

// ================= CSR build =================
__global__ void k_hist(const int* __restrict__ ei) {
    int e = blockIdx.x * blockDim.x + threadIdx.x;
    if (e < NE) atomicAdd(&g_deg[ei[NE + e]], 1);
}
__global__ void k_scan() {
    __shared__ int s[1024];
    const int CH = (NN + 1023) / 1024;
    int t = threadIdx.x, base = t * CH, sum = 0;
    for (int i = 0; i < CH; i++) { int idx = base + i; sum += (idx < NN) ? g_deg[idx] : 0; }
    s[t] = sum; __syncthreads();
    for (int off = 1; off < 1024; off <<= 1) {
        int v = (t >= off) ? s[t - off] : 0; __syncthreads();
        s[t] += v; __syncthreads();
    }
    int run = (t == 0) ? 0 : s[t - 1];
    for (int i = 0; i < CH; i++) {
        int idx = base + i;
        if (idx < NN) { g_rowptr[idx] = run; run += g_deg[idx]; }
    }
    if (t == 1023) g_rowptr[NN] = s[1023];
}
__global__ void k_scatter(const int* __restrict__ ei, const float* __restrict__ ea) {
    int e = blockIdx.x * blockDim.x + threadIdx.x;
    if (e >= NE) return;
    int src = ei[e], dst = ei[NE + e];
    int pos = g_rowptr[dst] + atomicAdd(&g_cursor[dst], 1);
    g_srcs[pos] = src; g_wgts[pos] = ea[e];
}

// ================= fused prep: zero counts + weight splits + x->fp16 =================
#define W1_ELEMS (F0 * F1)   // 65536
#define W2_ELEMS (F1 * F1)   // 262144
#define PREP_W (2 * W1_ELEMS + 2 * W2_ELEMS)           // 655360
#define PREP_Z (PREP_W + NN)                           // +25000
#define PREP_X (PREP_Z + NN * F0)                      // +3200000
__global__ void k_prep(const float* __restrict__ W1_rel, const float* __restrict__ W1_root,
                       const float* __restrict__ W2_rel, const float* __restrict__ W2_root,
                       const float* __restrict__ x) {
    int i = blockIdx.x * blockDim.x + threadIdx.x;
    if (i < PREP_W) {
        const float* W; __half* th; __half* tl; int K, idx;
        if (i < W1_ELEMS) { W = W1_rel; th = g_w1rh; tl = g_w1rl; K = F0; idx = i; }
        else if (i < 2 * W1_ELEMS) { W = W1_root; th = g_w1th; tl = g_w1tl; K = F0; idx = i - W1_ELEMS; }
        else if (i < 2 * W1_ELEMS + W2_ELEMS) { W = W2_rel; th = g_w2rh; tl = g_w2rl; K = F1; idx = i - 2 * W1_ELEMS; }
        else { W = W2_root; th = g_w2th; tl = g_w2tl; K = F1; idx = i - 2 * W1_ELEMS - W2_ELEMS; }
        int k = idx / F1, n = idx % F1;   // all weights are [K, 512]
        split2h(W[idx], th[n * K + k], tl[n * K + k]);
    } else if (i < PREP_Z) {
        int n = i - PREP_W;
        g_deg[n] = 0; g_cursor[n] = 0;
    } else if (i < PREP_X) {
        int n = i - PREP_Z;
        g_x16[n] = __float2half_rn(x[n]);
    }
}

// ================= aggregation (gather-side, atomic-free) =================
// gather x in fp16; accumulate fp32
__global__ void k_agg128() {
    int node = blockIdx.x * 4 + (threadIdx.x >> 5);
    if (node >= NN) return;
    int lane = threadIdx.x & 31;
    int beg = g_rowptr[node], end = g_rowptr[node + 1];
    float acc0 = 0.f, acc1 = 0.f, acc2 = 0.f, acc3 = 0.f;
    for (int p = beg; p < end; p++) {
        int s = g_srcs[p]; float w = g_wgts[p];
        uint2 raw = *reinterpret_cast<const uint2*>(&g_x16[s * F0 + lane * 4]);
        __half2 v01 = *reinterpret_cast<__half2*>(&raw.x);
        __half2 v23 = *reinterpret_cast<__half2*>(&raw.y);
        float2 f01 = __half22float2(v01), f23 = __half22float2(v23);
        acc0 += w * f01.x; acc1 += w * f01.y; acc2 += w * f23.x; acc3 += w * f23.y;
    }
    int o = node * F0 + lane * 4;
    __half2* dst = reinterpret_cast<__half2*>(&g_a1[o]);
    dst[0] = __floats2half2_rn(acc0, acc1);
    dst[1] = __floats2half2_rn(acc2, acc3);
}
// gather h1 in fp16; accumulate fp32
__global__ void k_agg512() {
    int node = blockIdx.x, f4 = threadIdx.x;  // 128 threads, 4 halves each
    int beg = g_rowptr[node], end = g_rowptr[node + 1];
    float acc0 = 0.f, acc1 = 0.f, acc2 = 0.f, acc3 = 0.f;
    for (int p = beg; p < end; p++) {
        int s = g_srcs[p]; float w = g_wgts[p];
        uint2 raw = *reinterpret_cast<const uint2*>(&g_h116[(size_t)s * F1 + f4 * 4]);
        __half2 v01 = *reinterpret_cast<__half2*>(&raw.x);
        __half2 v23 = *reinterpret_cast<__half2*>(&raw.y);
        float2 f01 = __half22float2(v01), f23 = __half22float2(v23);
        acc0 += w * f01.x; acc1 += w * f01.y; acc2 += w * f23.x; acc3 += w * f23.y;
    }
    size_t o = (size_t)node * F1 + f4 * 4;
    __half2* dst = reinterpret_cast<__half2*>(&g_a2[o]);
    dst[0] = __floats2half2_rn(acc0, acc1);
    dst[1] = __floats2half2_rn(acc2, acc3);
}

// ================= tensor-core dual GEMM, fp16 A + split-weight B (2 passes) =================
#define CHK 64
#define PAD 72                       // fp16 row pitch (conflict-free ldmatrix)
#define ARR_BYTES (128 * PAD * 2)    // 18432
#define STG_BYTES (3 * ARR_BYTES)    // 55296 (A, Bh, Bl)
#define SMEM_BYTES (2 * STG_BYTES)   // 110592

__global__ __launch_bounds__(256) void k_gemm_tc(
    const __half* __restrict__ A1, const __half* __restrict__ B1h, const __half* __restrict__ B1l,
    const __half* __restrict__ A2, const __half* __restrict__ B2h, const __half* __restrict__ B2l,
    int K, const float* __restrict__ bias,
    __half* __restrict__ C16,
    int M, int Nc) {
    extern __shared__ char smem[];
    uint32_t sb = smem_u32(smem);
    int tid = threadIdx.x;
    int wid = tid >> 5, lane = tid & 31;
    int warpM = wid >> 2, warpN = wid & 3;   // 2 x 4
    int m0 = blockIdx.y * 128, n0 = blockIdx.x * 128;

    float acc[4][4][4];
#pragma unroll
    for (int i = 0; i < 4; i++)
#pragma unroll
        for (int j = 0; j < 4; j++)
#pragma unroll
            for (int q = 0; q < 4; q++) acc[i][j][q] = 0.f;

    int ncpp = K / CHK;
    int NC = 2 * ncpp;

    // A ldmatrix x4: rows 0-15 across lanes 0-15, k halves via lane>>4
    uint32_t a_lane = (uint32_t)((lane & 15) * PAD + (lane >> 4) * 8) * 2;
    // B ldmatrix x4 (two n8 frags): bit3 -> k-group, bit4 -> +8 n-rows
    uint32_t b_lane = (uint32_t)(((lane & 7) + ((lane >> 4) << 3)) * PAD
                                 + ((lane >> 3) & 1) * 8) * 2;

    // cp.async chunk c -> stage stg: arrays {A, Bh, Bl}
    auto issue = [&](int c, int stg) {
        int ph = c / ncpp;
        int kk = (c % ncpp) * CHK;
        const __half* arr0 = ph ? A2 : A1;
        const __half* arr1 = ph ? B2h : B1h;
        const __half* arr2 = ph ? B2l : B1l;
        uint32_t sdst = sb + (uint32_t)stg * STG_BYTES;
#pragma unroll
        for (int i = 0; i < 12; i++) {
            int unit = i * 256 + tid;          // 0..3071
            int arr = unit >> 10;              // 0..2
            int rem = unit & 1023;
            int row = rem >> 3, cg = rem & 7;  // 128 rows x 8 col-groups (8 halves)
            uint32_t dst = sdst + (uint32_t)arr * ARR_BYTES + (uint32_t)(row * PAD + cg * 8) * 2;
            if (arr == 0) {
                int m = m0 + row;
                uint32_t sz = (m < M) ? 16u : 0u;
                int mc = (m < M) ? m : 0;
                cpa16(dst, arr0 + (size_t)mc * K + kk + cg * 8, sz);
            } else {
                const __half* base = (arr == 1) ? arr1 : arr2;
                cpa16(dst, base + (size_t)(n0 + row) * K + kk + cg * 8, 16u);
            }
        }
    };

    issue(0, 0);
    cp_commit();

    for (int c = 0; c < NC; c++) {
        cp_wait<0>();        // chunk c's loads arrived
        __syncthreads();     // all warps done consuming chunk c-1 -> its stage is free
        if (c + 1 < NC) { issue(c + 1, (c + 1) & 1); cp_commit(); }

        uint32_t sst = sb + (uint32_t)(c & 1) * STG_BYTES;
        uint32_t aA = sst + a_lane;
        uint32_t bH = sst + ARR_BYTES + b_lane, bL = sst + 2 * ARR_BYTES + b_lane;

#pragma unroll
        for (int ks = 0; ks < CHK / 16; ks++) {
            // B frags: 2 x ldm_x4 per array -> four n8 frags each
            uint32_t bh[4][2], bl[4][2];
#pragma unroll
            for (int np = 0; np < 2; np++) {   // nt pairs {0,1}, {2,3}
                uint32_t off = (uint32_t)((warpN * 32 + np * 16) * PAD + ks * 16) * 2;
                uint32_t r4[4];
                ldm_x4(r4, bH + off);
                bh[np * 2][0] = r4[0]; bh[np * 2][1] = r4[1];
                bh[np * 2 + 1][0] = r4[2]; bh[np * 2 + 1][1] = r4[3];
                ldm_x4(r4, bL + off);
                bl[np * 2][0] = r4[0]; bl[np * 2][1] = r4[1];
                bl[np * 2 + 1][0] = r4[2]; bl[np * 2 + 1][1] = r4[3];
            }
#pragma unroll
            for (int mt = 0; mt < 4; mt++) {
                uint32_t av[4];
                uint32_t off = (uint32_t)((warpM * 64 + mt * 16) * PAD + ks * 16) * 2;
                ldm_x4(av, aA + off);
#pragma unroll
                for (int nt = 0; nt < 4; nt++) {
                    mma_f16(acc[mt][nt], av, bh[nt]);
                    mma_f16(acc[mt][nt], av, bl[nt]);
                }
            }
        }
    }

    // epilogue: bias + relu -> packed fp16 stores
#pragma unroll
    for (int mt = 0; mt < 4; mt++) {
#pragma unroll
        for (int nt = 0; nt < 4; nt++) {
            int n = n0 + warpN * 32 + nt * 8 + (lane & 3) * 2;
            float b0 = __ldg(&bias[n]), b1v = __ldg(&bias[n + 1]);
#pragma unroll
            for (int h = 0; h < 2; h++) {
                int m = m0 + warpM * 64 + mt * 16 + (lane >> 2) + h * 8;
                if (m < M) {
                    size_t o = (size_t)m * Nc + n;
                    float v0 = fmaxf(acc[mt][nt][h * 2 + 0] + b0, 0.f);
                    float v1 = fmaxf(acc[mt][nt][h * 2 + 1] + b1v, 0.f);
                    *reinterpret_cast<__half2*>(&C16[o]) = __floats2half2_rn(v0, v1);
                }
            }
        }
    }
}

// ================= pooling (bounds folded in) + MLP head =================
__global__ void k_pool(const int* __restrict__ batch) {
    __shared__ int bounds[2];
    int g = blockIdx.x >> 2;
    int f = ((blockIdx.x & 3) << 7) + threadIdx.x;   // feature pair base = f*... (128 thr * 4 chunks)
    if (threadIdx.x < 2) {
        int target = g + threadIdx.x;
        int lo = 0, hi = NN;
        while (lo < hi) {
            int mid = (lo + hi) >> 1;
            if (batch[mid] < target) lo = mid + 1; else hi = mid;
        }
        bounds[threadIdx.x] = lo;
    }
    __syncthreads();
    int s0 = bounds[0], s1 = bounds[1];
    // each thread owns 1 half2 pair (features 2f, 2f+1): 128 thr * 4 blk-chunks * ... -> F1/2=256 pairs
    // grid: NG*4 blocks, 128 threads => 512 lanes per graph => one feature each via pairing:
    float accA = 0.f, accB = 0.f;
    for (int n = s0; n < s1; n++) {
        __half2 v = *reinterpret_cast<const __half2*>(&g_h216[(size_t)n * F1 + f * 2 - (f & 1) * 0]);
        (void)v;
        break;
    }
    // simple per-feature loop (f indexes a single feature 0..511 with blocks covering 4*128)
    float acc = 0.f;
    for (int n = s0; n < s1; n++) acc += __half2float(g_h216[(size_t)n * F1 + f]);
    accA = acc; (void)accB;
    g_gv[g * F1 + f] = accA / fmaxf((float)(s1 - s0), 1.0f);
}
__global__ void k_mlp(const float* __restrict__ Wl1, const float* __restrict__ bl1,
                      const float* __restrict__ Wl2, const float* __restrict__ bl2,
                      const float* __restrict__ Wl3, const float* __restrict__ bl3,
                      float* __restrict__ out) {
    int g = blockIdx.x, t = threadIdx.x;
    __shared__ float gv[F1], t1[64], t2[16];
    for (int i = t; i < F1; i += 64) gv[i] = g_gv[g * F1 + i];
    __syncthreads();
    float a = bl1[t];
    for (int k = 0; k < F1; k++) a += gv[k] * Wl1[k * 64 + t];
    t1[t] = fmaxf(a, 0.f);
    __syncthreads();
    if (t < 16) {
        float a2 = bl2[t];
        for (int k = 0; k < 64; k++) a2 += t1[k] * Wl2[k * 16 + t];
        t2[t] = fmaxf(a2, 0.f);
    }
    __syncthreads();
    if (t == 0) {
        float a3 = bl3[0];
        for (int k = 0; k < 16; k++) a3 += t2[k] * Wl3[k];
        out[g] = a3;
    }
}

// ================= launch =================
extern "C" void kernel_launch(void* const* d_in, const int* in_sizes, int n_in,
                              void* d_out, int out_size) {
    const float* x       = (const float*)d_in[0];
    const int*   ei      = (const int*)d_in[1];
    const float* ea      = (const float*)d_in[2];
    const int*   batch   = (const int*)d_in[3];
    const float* W1_rel  = (const float*)d_in[4];
    const float* b1      = (const float*)d_in[5];
    const float* W1_root = (const float*)d_in[6];
    const float* W2_rel  = (const float*)d_in[7];
    const float* b2      = (const float*)d_in[8];
    const float* W2_root = (const float*)d_in[9];
    const float* Wl1     = (const float*)d_in[10];
    const float* bl1     = (const float*)d_in[11];
    const float* Wl2     = (const float*)d_in[12];
    const float* bl2     = (const float*)d_in[13];
    const float* Wl3     = (const float*)d_in[14];
    const float* bl3     = (const float*)d_in[15];
    float* out = (float*)d_out;

    cudaFuncSetAttribute(k_gemm_tc, cudaFuncAttributeMaxDynamicSharedMemorySize, SMEM_BYTES);

#define SYM(T, p, s) T* p; cudaGetSymbolAddress((void**)&p, s)
    SYM(__half, x16, g_x16);  SYM(__half, a1, g_a1);
    SYM(__half, h116, g_h116);
    SYM(__half, a2, g_a2);    SYM(__half, h216, g_h216);
    SYM(__half, w1rh, g_w1rh); SYM(__half, w1rl, g_w1rl);
    SYM(__half, w1th, g_w1th); SYM(__half, w1tl, g_w1tl);
    SYM(__half, w2rh, g_w2rh); SYM(__half, w2rl, g_w2rl);
    SYM(__half, w2th, g_w2th); SYM(__half, w2tl, g_w2tl);
#undef SYM

    // prep (zero counts + weight splits + x->fp16)
    k_prep<<<(PREP_X + 255) / 256, 256>>>(W1_rel, W1_root, W2_rel, W2_root, x);

    // CSR build
    k_hist<<<(NE + 255) / 256, 256>>>(ei);
    k_scan<<<1, 1024>>>();
    k_scatter<<<(NE + 255) / 256, 256>>>(ei, ea);

    // layer 1: h1(fp16) = relu(agg1@W1_rel + x@W1_root + b1)
    k_agg128<<<(NN + 3) / 4, 128>>>();
    {
        dim3 grid(F1 / 128, (NN + 127) / 128);
        k_gemm_tc<<<grid, 256, SMEM_BYTES>>>(a1, w1rh, w1rl, x16, w1th, w1tl,
                                             F0, b1, h116, NN, F1);
    }
    // layer 2: h2(fp16) = relu(agg2@W2_rel + h1@W2_root + b2)
    k_agg512<<<NN, 128>>>();
    {
        dim3 grid(F1 / 128, (NN + 127) / 128);
        k_gemm_tc<<<grid, 256, SMEM_BYTES>>>(a2, w2rh, w2rl, h116, w2th, w2tl,
                                             F1, b2, h216, NN, F1);
    }
    // pool (+bounds) + head
    k_pool<<<NG * 4, 128>>>(batch);
    k_mlp<<<NG, 64>>>(Wl1, bl1, Wl2, bl2, Wl3, bl3, out);
    (void)in_sizes; (void)n_in; (void)out_size;
}